// round 9
// baseline (speedup 1.0000x reference)
#include <cuda_runtime.h>
#include <cuda_bf16.h>
#include <cstdint>

#define BATCH 16
#define C_IN  256
#define HW    4096
#define C8    32
#define C2    128
#define MPOOL 1024
#define CPROJ 192   // 32 theta + 32 phi + 128 g

// ---------------- scratch (device globals; no allocation allowed) ----------
__device__ float         d_theta[BATCH * HW * C8];     // [b][n][k]  (tf32-rounded)
__device__ float         d_phi[BATCH * C8 * MPOOL];    // [b][k][m]  (tf32-rounded)
__device__ __nv_bfloat16 d_gT[BATCH * C2 * MPOOL];     // [b][d][m]
__device__ __nv_bfloat16 d_wfb[C_IN * C2];             // bf16 copy of w_final

// ---------------- helpers ---------------------------------------------------
__device__ __forceinline__ float tf32r(float f) {
    uint32_t u;
    asm("cvt.rna.tf32.f32 %0, %1;" : "=r"(u) : "f"(f));
    return __uint_as_float(u);
}

__device__ __forceinline__ float ex2(float x) {
    float y;
    asm("ex2.approx.ftz.f32 %0, %1;" : "=f"(y) : "f"(x));
    return y;
}

__device__ __forceinline__ void mma_tf32(float* d, const uint32_t* a,
                                         uint32_t b0, uint32_t b1) {
    asm volatile(
        "mma.sync.aligned.m16n8k8.row.col.f32.tf32.tf32.f32 "
        "{%0,%1,%2,%3}, {%4,%5,%6,%7}, {%8,%9}, {%0,%1,%2,%3};"
        : "+f"(d[0]), "+f"(d[1]), "+f"(d[2]), "+f"(d[3])
        : "r"(a[0]), "r"(a[1]), "r"(a[2]), "r"(a[3]), "r"(b0), "r"(b1));
}

__device__ __forceinline__ void mma_bf16(float* d, const uint32_t* a,
                                         uint32_t b0, uint32_t b1) {
    asm volatile(
        "mma.sync.aligned.m16n8k16.row.col.f32.bf16.bf16.f32 "
        "{%0,%1,%2,%3}, {%4,%5,%6,%7}, {%8,%9}, {%0,%1,%2,%3};"
        : "+f"(d[0]), "+f"(d[1]), "+f"(d[2]), "+f"(d[3])
        : "r"(a[0]), "r"(a[1]), "r"(a[2]), "r"(a[3]), "r"(b0), "r"(b1));
}

__device__ __forceinline__ void ldsm_x4(uint32_t& r0, uint32_t& r1,
                                        uint32_t& r2, uint32_t& r3, uint32_t a) {
    asm volatile("ldmatrix.sync.aligned.m8n8.x4.shared.b16 {%0,%1,%2,%3}, [%4];"
                 : "=r"(r0), "=r"(r1), "=r"(r2), "=r"(r3) : "r"(a));
}
__device__ __forceinline__ void ldsm_x2(uint32_t& r0, uint32_t& r1, uint32_t a) {
    asm volatile("ldmatrix.sync.aligned.m8n8.x2.shared.b16 {%0,%1}, [%2];"
                 : "=r"(r0), "=r"(r1) : "r"(a));
}

__device__ __forceinline__ uint32_t pack_bf16(float a, float b) {
    __nv_bfloat162 h = __floats2bfloat162_rn(a, b);
    return *reinterpret_cast<uint32_t*>(&h);
}

__device__ __forceinline__ void cp16(uint32_t smem, const void* g) {
    asm volatile("cp.async.cg.shared.global [%0], [%1], 16;\n"
                 :: "r"(smem), "l"(g));
}
__device__ __forceinline__ void cp_commit() {
    asm volatile("cp.async.commit_group;\n");
}
template <int N>
__device__ __forceinline__ void cp_wait() {
    asm volatile("cp.async.wait_group %0;\n" :: "n"(N));
}
__device__ __forceinline__ void prefetch_l2(const void* p) {
    asm volatile("prefetch.global.L2 [%0];" :: "l"(p));
}

#define LOG2E 1.4426950408889634f

// =============================================================================
// K1: projection GEMM + fused 2x2 maxpool, 3-stage cp.async pipeline.
// 256 threads, 8 warps (2m x 4n), warp tile 96x32. tf32 mma.
// Also converts its 64-element slice of w_final to bf16 (wfconv folded in).
// =============================================================================
#define PJ_A_F   (192 * 40)
#define PJ_B_F   (32 * 132)
#define PJ_STAGE (PJ_A_F + PJ_B_F)           // floats
#define PJ_SMEM_B (3 * PJ_STAGE * 4)         // 142848 bytes (>= ytile 160*132*4)

__device__ __forceinline__ void proj_load(uint32_t a_s, uint32_t b_s,
                                          const float* wth, const float* wph,
                                          const float* wg, const float* xb,
                                          int kc, int p0, int tid) {
#pragma unroll
    for (int i = 0; i < 6; i++) {        // A: 192 rows x 32 floats
        int c = tid + i * 256;
        int r = c >> 3, q = c & 7;
        const float* src = (r < 32) ? wth + r * 256
                        : (r < 64) ? wph + (r - 32) * 256
                                   : wg + (r - 64) * 256;
        cp16(a_s + (r * 40 + q * 4) * 4, src + kc * 32 + q * 4);
    }
#pragma unroll
    for (int i = 0; i < 4; i++) {        // B: 32 rows x 128 floats
        int c = tid + i * 256;
        int kk = c >> 5, j4 = c & 31;
        cp16(b_s + (kk * 132 + j4 * 4) * 4,
             xb + (size_t)(kc * 32 + kk) * HW + p0 + j4 * 4);
    }
}

__global__ __launch_bounds__(256, 1)
void proj_kernel(const float* __restrict__ x,
                 const float* __restrict__ wth,
                 const float* __restrict__ wph,
                 const float* __restrict__ wg,
                 const float* __restrict__ wf) {
    extern __shared__ float sm[];
    const uint32_t sm_u = (uint32_t)__cvta_generic_to_shared(sm);

    const int b   = blockIdx.y;
    const int p0  = blockIdx.x * 128;
    const int tid = threadIdx.x;
    const int w   = tid >> 5, lane = tid & 31;
    const int g   = lane >> 2, tig = lane & 3;
    const int wm  = w >> 2, wn = w & 3;
    const int m0w = wm * 96, n0w = wn * 32;

    // ---- folded wfconv: this block's 64-element slice of w_final ----
    {
        int blk = b * 32 + blockIdx.x;            // 0..511
        if (tid < 16) {
            int e0 = blk * 64 + tid * 4;
            float4 v = *reinterpret_cast<const float4*>(&wf[e0]);
            uint2 pk = make_uint2(pack_bf16(v.x, v.y), pack_bf16(v.z, v.w));
            *reinterpret_cast<uint2*>(&d_wfb[e0]) = pk;
        }
    }

    float acc[6][4][4];
#pragma unroll
    for (int mt = 0; mt < 6; mt++)
#pragma unroll
        for (int nt = 0; nt < 4; nt++)
#pragma unroll
            for (int j = 0; j < 4; j++) acc[mt][nt][j] = 0.f;

    const float* xb = x + (size_t)b * C_IN * HW;

    proj_load(sm_u, sm_u + PJ_A_F * 4, wth, wph, wg, xb, 0, p0, tid);
    cp_commit();
    proj_load(sm_u + PJ_STAGE * 4, sm_u + (PJ_STAGE + PJ_A_F) * 4,
              wth, wph, wg, xb, 1, p0, tid);
    cp_commit();

    for (int kc = 0; kc < 8; kc++) {
        const int cur = kc % 3;
        if (kc + 2 < 8) {
            const int nst = (kc + 2) % 3;
            proj_load(sm_u + nst * PJ_STAGE * 4,
                      sm_u + (nst * PJ_STAGE + PJ_A_F) * 4,
                      wth, wph, wg, xb, kc + 2, p0, tid);
            cp_commit();
            cp_wait<2>();
        } else if (kc + 1 < 8) {
            cp_wait<1>();
        } else {
            cp_wait<0>();
        }
        __syncthreads();

        const float* Ac = sm + cur * PJ_STAGE;
        const float* Bc = sm + cur * PJ_STAGE + PJ_A_F;
#pragma unroll
        for (int ks = 0; ks < 4; ks++) {
            uint32_t a[6][4];
#pragma unroll
            for (int mt = 0; mt < 6; mt++) {
                int r = m0w + mt * 16;
                a[mt][0] = __float_as_uint(Ac[(r + g)     * 40 + ks * 8 + tig]);
                a[mt][1] = __float_as_uint(Ac[(r + g + 8) * 40 + ks * 8 + tig]);
                a[mt][2] = __float_as_uint(Ac[(r + g)     * 40 + ks * 8 + tig + 4]);
                a[mt][3] = __float_as_uint(Ac[(r + g + 8) * 40 + ks * 8 + tig + 4]);
            }
#pragma unroll
            for (int nt = 0; nt < 4; nt++) {
                uint32_t b0 = __float_as_uint(Bc[(ks * 8 + tig)     * 132 + n0w + nt * 8 + g]);
                uint32_t b1 = __float_as_uint(Bc[(ks * 8 + tig + 4) * 132 + n0w + nt * 8 + g]);
#pragma unroll
                for (int mt = 0; mt < 6; mt++) mma_tf32(acc[mt][nt], a[mt], b0, b1);
            }
        }
        __syncthreads();
    }

    // ---- epilogue: theta direct (transposed, rna); phi/g into smem ytile ----
    float* ytile = sm;   // 160 ch x 132 floats; staging buffers dead
    float* thb = d_theta + (size_t)b * HW * C8;
#pragma unroll
    for (int mt = 0; mt < 6; mt++)
#pragma unroll
        for (int nt = 0; nt < 4; nt++) {
            int pl = n0w + nt * 8 + tig * 2;
            int p  = p0 + pl;
            int c0 = m0w + mt * 16 + g;
            int c1 = c0 + 8;
            if (c0 < 32) {
                thb[(size_t)p * 32 + c0]       = tf32r(acc[mt][nt][0]);
                thb[(size_t)(p + 1) * 32 + c0] = tf32r(acc[mt][nt][1]);
                thb[(size_t)p * 32 + c1]       = tf32r(acc[mt][nt][2]);
                thb[(size_t)(p + 1) * 32 + c1] = tf32r(acc[mt][nt][3]);
            } else {
                ytile[(c0 - 32) * 132 + pl]     = acc[mt][nt][0];
                ytile[(c0 - 32) * 132 + pl + 1] = acc[mt][nt][1];
                ytile[(c1 - 32) * 132 + pl]     = acc[mt][nt][2];
                ytile[(c1 - 32) * 132 + pl + 1] = acc[mt][nt][3];
            }
        }
    __syncthreads();

    const int m0 = (p0 >> 2);
#pragma unroll
    for (int i = 0; i < 20; i++) {
        int idx = tid + i * 256;
        int ch = idx >> 5, wp = idx & 31;
        const float* r0 = &ytile[ch * 132 + wp * 2];
        float v = fmaxf(fmaxf(r0[0], r0[1]), fmaxf(r0[64], r0[65]));
        if (ch < 32)
            d_phi[((size_t)b * 32 + ch) * MPOOL + m0 + wp] = tf32r(v);
        else
            d_gT[((size_t)b * C2 + (ch - 32)) * MPOOL + m0 + wp] = __float2bfloat16(v);
    }
}

// =============================================================================
// K2: fused flash attention + final 1x1 conv + residual.
// Mainloop: round-5 proven (256 thr, 8 warps, KB=64, 3-stage cp.async).
// New: x tile L2-prefetched during mainloop; wf group committed after tiles.
// =============================================================================
#define KB       64
#define NTILE    (MPOOL / KB)        // 16
#define PH_STR   68
#define G_STR    72
#define PH_BYTES (32 * PH_STR * 4)   // 8704
#define G_BYTES  (128 * G_STR * 2)   // 18432
#define K2_STAGE (PH_BYTES + G_BYTES)
#define K2_STG_T (3 * K2_STAGE)      // 81408 (also holds Osm 128*136*2=34816)
#define WF_STR   136
#define WF_BYTES (256 * WF_STR * 2)  // 69632
#define K2_SMEM  (K2_STG_T + WF_BYTES)  // 151040

__device__ __forceinline__ void attn_load_tile(uint32_t stage_base,
                                               const float* phb,
                                               const __nv_bfloat16* gTb,
                                               int mb, int tid) {
    const uint32_t ph_s = stage_base;
    const uint32_t g_s  = stage_base + PH_BYTES;
#pragma unroll
    for (int i = 0; i < 2; i++) {
        int c = tid + i * 256;
        int r = c >> 4, col = c & 15;
        cp16(ph_s + r * (PH_STR * 4) + col * 16,
             phb + (size_t)r * MPOOL + mb + col * 4);
    }
#pragma unroll
    for (int i = 0; i < 4; i++) {
        int c = tid + i * 256;
        int r = c >> 3, col = c & 7;
        cp16(g_s + r * (G_STR * 2) + col * 16,
             gTb + (size_t)r * MPOOL + mb + col * 8);
    }
}

__global__ __launch_bounds__(256, 1)
void attn_kernel(const float* __restrict__ x,
                 const float* __restrict__ sigp,
                 float* __restrict__ out) {
    extern __shared__ char smraw[];
    const uint32_t smem_u32 = (uint32_t)__cvta_generic_to_shared(smraw);
    const uint32_t wf_u = smem_u32 + K2_STG_T;

    const int b   = blockIdx.y, qt = blockIdx.x;
    const int tid = threadIdx.x;
    const int w   = tid >> 5, lane = tid & 31;
    const int g   = lane >> 2, tig = lane & 3;
    const int n0  = qt * 128 + w * 16;

    const float*         phb = d_phi + (size_t)b * 32 * MPOOL;
    const __nv_bfloat16* gTb = d_gT + (size_t)b * C2 * MPOOL;

    uint32_t at[4][4];
    {
        const float* th = d_theta + ((size_t)b * HW + n0) * 32;
#pragma unroll
        for (int ks = 0; ks < 4; ks++) {
            at[ks][0] = __float_as_uint(th[g * 32       + ks * 8 + tig]);
            at[ks][1] = __float_as_uint(th[(g + 8) * 32 + ks * 8 + tig]);
            at[ks][2] = __float_as_uint(th[g * 32       + ks * 8 + tig + 4]);
            at[ks][3] = __float_as_uint(th[(g + 8) * 32 + ks * 8 + tig + 4]);
        }
    }

    float O[16][4];
#pragma unroll
    for (int df = 0; df < 16; df++)
#pragma unroll
        for (int j = 0; j < 4; j++) O[df][j] = 0.f;
    float lsum0 = 0.f, lsum1 = 0.f;

    // tiles first (critical path), then wf (needed only at epilogue)
    attn_load_tile(smem_u32, phb, gTb, 0, tid);
    cp_commit();
    attn_load_tile(smem_u32 + K2_STAGE, phb, gTb, KB, tid);
    cp_commit();
#pragma unroll
    for (int i = 0; i < 16; i++) {
        int c = tid + i * 256;
        int r = c >> 4, q = c & 15;
        cp16(wf_u + (r * WF_STR + q * 8) * 2, d_wfb + (size_t)r * C2 + q * 8);
    }
    cp_commit();

    for (int kb = 0; kb < NTILE; kb++) {
        const int cur = kb % 3;
        if (kb + 2 < NTILE) {
            attn_load_tile(smem_u32 + ((kb + 2) % 3) * K2_STAGE,
                           phb, gTb, (kb + 2) * KB, tid);
            cp_commit();
            cp_wait<2>();
        } else if (kb + 1 < NTILE) {
            cp_wait<1>();
        } else {
            cp_wait<0>();
        }
        __syncthreads();

        // L2-prefetch this CTA's x output tile (1024 lines over kb=0..3)
        if (kb < 4) {
            int line = kb * 256 + tid;
            int row = line >> 2, seg = line & 3;
            prefetch_l2(x + ((size_t)b * 256 + row) * HW + qt * 128 + seg * 32);
        }

        const uint32_t phc = smem_u32 + cur * K2_STAGE;
        const uint32_t gc  = phc + PH_BYTES;

        float S[8][4];
#pragma unroll
        for (int nf = 0; nf < 8; nf++)
            S[nf][0] = S[nf][1] = S[nf][2] = S[nf][3] = 0.f;
#pragma unroll
        for (int ks = 0; ks < 4; ks++) {
#pragma unroll
            for (int nf = 0; nf < 8; nf++) {
                uint32_t b0, b1;
                uint32_t a0 = phc + ((ks * 8 + tig) * PH_STR + nf * 8 + g) * 4;
                asm volatile("ld.shared.b32 %0, [%1];" : "=r"(b0) : "r"(a0));
                asm volatile("ld.shared.b32 %0, [%1];" : "=r"(b1) : "r"(a0 + 4 * PH_STR * 4));
                mma_tf32(S[nf], at[ks], b0, b1);
            }
        }

#pragma unroll
        for (int nf = 0; nf < 8; nf++) {
            S[nf][0] = ex2(S[nf][0] * LOG2E);
            S[nf][1] = ex2(S[nf][1] * LOG2E);
            S[nf][2] = ex2(S[nf][2] * LOG2E);
            S[nf][3] = ex2(S[nf][3] * LOG2E);
            lsum0 += S[nf][0] + S[nf][1];
            lsum1 += S[nf][2] + S[nf][3];
        }

        uint32_t P[4][4];
#pragma unroll
        for (int kf = 0; kf < 4; kf++) {
            P[kf][0] = pack_bf16(S[2 * kf][0],     S[2 * kf][1]);
            P[kf][1] = pack_bf16(S[2 * kf][2],     S[2 * kf][3]);
            P[kf][2] = pack_bf16(S[2 * kf + 1][0], S[2 * kf + 1][1]);
            P[kf][3] = pack_bf16(S[2 * kf + 1][2], S[2 * kf + 1][3]);
        }

#pragma unroll
        for (int pair = 0; pair < 2; pair++) {
#pragma unroll
            for (int df = 0; df < 16; df++) {
                uint32_t r0, r1, r2, r3;
                uint32_t addr = gc +
                    ((df * 8 + (lane & 7)) * G_STR + pair * 32 + (lane >> 3) * 8) * 2;
                ldsm_x4(r0, r1, r2, r3, addr);
                mma_bf16(O[df], P[2 * pair],     r0, r1);
                mma_bf16(O[df], P[2 * pair + 1], r2, r3);
            }
        }
        __syncthreads();
    }

    // ---- normalize, O -> Osm (bf16, stride 136; staging area is dead) ----
    lsum0 += __shfl_xor_sync(0xffffffffu, lsum0, 1);
    lsum0 += __shfl_xor_sync(0xffffffffu, lsum0, 2);
    lsum1 += __shfl_xor_sync(0xffffffffu, lsum1, 1);
    lsum1 += __shfl_xor_sync(0xffffffffu, lsum1, 2);
    const float i0 = 1.f / lsum0, i1 = 1.f / lsum1;

    const uint32_t osm = smem_u32;
#pragma unroll
    for (int df = 0; df < 16; df++) {
        uint32_t v0 = pack_bf16(O[df][0] * i0, O[df][1] * i0);
        uint32_t v1 = pack_bf16(O[df][2] * i1, O[df][3] * i1);
        uint32_t a0 = osm + ((w * 16 + g) * WF_STR + df * 8 + tig * 2) * 2;
        asm volatile("st.shared.b32 [%0], %1;" :: "r"(a0), "r"(v0));
        asm volatile("st.shared.b32 [%0], %1;" :: "r"(a0 + 8 * WF_STR * 2), "r"(v1));
    }
    __syncthreads();

    // ---- final conv: out[256co x 128p] = sigma * wf @ Osm^T + x ----
    const float sig = *sigp;
    const int wm = w >> 1, wn = w & 1;
    const int cw = wm * 32, pw = wn * 64;

#pragma unroll
    for (int half = 0; half < 2; half++) {
        const int co0 = half * 128;
        float acc[2][8][4];
#pragma unroll
        for (int mt = 0; mt < 2; mt++)
#pragma unroll
            for (int nt = 0; nt < 8; nt++)
#pragma unroll
                for (int j = 0; j < 4; j++) acc[mt][nt][j] = 0.f;

#pragma unroll
        for (int k16 = 0; k16 < 8; k16++) {
            uint32_t a[2][4];
#pragma unroll
            for (int mt = 0; mt < 2; mt++) {
                uint32_t addr = wf_u +
                    ((co0 + cw + mt * 16 + (lane & 15)) * WF_STR + k16 * 16 + (lane >> 4) * 8) * 2;
                ldsm_x4(a[mt][0], a[mt][1], a[mt][2], a[mt][3], addr);
            }
            uint32_t bq[8][2];
#pragma unroll
            for (int nt = 0; nt < 8; nt++) {
                uint32_t addr = osm +
                    ((pw + nt * 8 + (lane & 7)) * WF_STR + k16 * 16 + ((lane >> 3) & 1) * 8) * 2;
                ldsm_x2(bq[nt][0], bq[nt][1], addr);
            }
#pragma unroll
            for (int nt = 0; nt < 8; nt++)
#pragma unroll
                for (int mt = 0; mt < 2; mt++)
                    mma_bf16(acc[mt][nt], a[mt], bq[nt][0], bq[nt][1]);
        }

#pragma unroll
        for (int mt = 0; mt < 2; mt++)
#pragma unroll
            for (int nt = 0; nt < 8; nt++) {
                int co = co0 + cw + mt * 16 + g;
                int p  = qt * 128 + pw + nt * 8 + tig * 2;
                {
                    size_t off = ((size_t)b * 256 + co) * HW + p;
                    float2 xv = *reinterpret_cast<const float2*>(&x[off]);
                    float2 ov = make_float2(sig * acc[mt][nt][0] + xv.x,
                                            sig * acc[mt][nt][1] + xv.y);
                    *reinterpret_cast<float2*>(&out[off]) = ov;
                }
                {
                    size_t off = ((size_t)b * 256 + co + 8) * HW + p;
                    float2 xv = *reinterpret_cast<const float2*>(&x[off]);
                    float2 ov = make_float2(sig * acc[mt][nt][2] + xv.x,
                                            sig * acc[mt][nt][3] + xv.y);
                    *reinterpret_cast<float2*>(&out[off]) = ov;
                }
            }
    }
}

// =============================================================================
extern "C" void kernel_launch(void* const* d_in, const int* in_sizes, int n_in,
                              void* d_out, int out_size) {
    (void)in_sizes; (void)n_in; (void)out_size;
    const float* x    = (const float*)d_in[0];
    const float* wth  = (const float*)d_in[1];
    const float* wph  = (const float*)d_in[2];
    const float* wg   = (const float*)d_in[3];
    const float* wf   = (const float*)d_in[4];
    const float* sig  = (const float*)d_in[5];
    float*       out  = (float*)d_out;

    cudaFuncSetAttribute(proj_kernel,
                         cudaFuncAttributeMaxDynamicSharedMemorySize, PJ_SMEM_B);
    cudaFuncSetAttribute(attn_kernel,
                         cudaFuncAttributeMaxDynamicSharedMemorySize, K2_SMEM);

    proj_kernel<<<dim3(32, 16), 256, PJ_SMEM_B>>>(x, wth, wph, wg, wf);
    attn_kernel<<<dim3(32, 16), 256, K2_SMEM>>>(x, sig, out);
}

// round 10
// speedup vs baseline: 1.2338x; 1.2338x over previous
#include <cuda_runtime.h>
#include <cuda_bf16.h>
#include <cstdint>

#define BATCH 16
#define C_IN  256
#define HW    4096
#define C8    32
#define C2    128
#define MPOOL 1024
#define CPROJ 192   // 32 theta + 32 phi + 128 g

// ---------------- scratch (device globals; no allocation allowed) ----------
// d_phi is stored in mma-B-fragment order: per batch 16 key-tiles, per tile
// 32 lanes x 64 floats: value(lane=g*4+tig, i=nf*8+ks*2+b) = phi[kk=ks*8+tig+4b][key=nf*8+g]
__device__ float         d_theta[BATCH * HW * C8];     // [b][n][k]  (tf32-rounded)
__device__ float         d_phi[BATCH * C8 * MPOOL];    // frag-ordered (see above)
__device__ __nv_bfloat16 d_gT[BATCH * C2 * MPOOL];     // [b][d][m]
__device__ __nv_bfloat16 d_wfb[C_IN * C2];             // bf16 copy of w_final

// ---------------- helpers ---------------------------------------------------
__device__ __forceinline__ float tf32r(float f) {
    uint32_t u;
    asm("cvt.rna.tf32.f32 %0, %1;" : "=r"(u) : "f"(f));
    return __uint_as_float(u);
}

__device__ __forceinline__ float ex2(float x) {
    float y;
    asm("ex2.approx.ftz.f32 %0, %1;" : "=f"(y) : "f"(x));
    return y;
}

__device__ __forceinline__ void mma_tf32(float* d, const uint32_t* a,
                                         uint32_t b0, uint32_t b1) {
    asm volatile(
        "mma.sync.aligned.m16n8k8.row.col.f32.tf32.tf32.f32 "
        "{%0,%1,%2,%3}, {%4,%5,%6,%7}, {%8,%9}, {%0,%1,%2,%3};"
        : "+f"(d[0]), "+f"(d[1]), "+f"(d[2]), "+f"(d[3])
        : "r"(a[0]), "r"(a[1]), "r"(a[2]), "r"(a[3]), "r"(b0), "r"(b1));
}

__device__ __forceinline__ void mma_bf16(float* d, const uint32_t* a,
                                         uint32_t b0, uint32_t b1) {
    asm volatile(
        "mma.sync.aligned.m16n8k16.row.col.f32.bf16.bf16.f32 "
        "{%0,%1,%2,%3}, {%4,%5,%6,%7}, {%8,%9}, {%0,%1,%2,%3};"
        : "+f"(d[0]), "+f"(d[1]), "+f"(d[2]), "+f"(d[3])
        : "r"(a[0]), "r"(a[1]), "r"(a[2]), "r"(a[3]), "r"(b0), "r"(b1));
}

__device__ __forceinline__ void ldsm_x4(uint32_t& r0, uint32_t& r1,
                                        uint32_t& r2, uint32_t& r3, uint32_t a) {
    asm volatile("ldmatrix.sync.aligned.m8n8.x4.shared.b16 {%0,%1,%2,%3}, [%4];"
                 : "=r"(r0), "=r"(r1), "=r"(r2), "=r"(r3) : "r"(a));
}
__device__ __forceinline__ void ldsm_x2(uint32_t& r0, uint32_t& r1, uint32_t a) {
    asm volatile("ldmatrix.sync.aligned.m8n8.x2.shared.b16 {%0,%1}, [%2];"
                 : "=r"(r0), "=r"(r1) : "r"(a));
}

__device__ __forceinline__ void lds_v4(uint32_t& r0, uint32_t& r1,
                                       uint32_t& r2, uint32_t& r3, uint32_t a) {
    asm volatile("ld.shared.v4.b32 {%0,%1,%2,%3}, [%4];"
                 : "=r"(r0), "=r"(r1), "=r"(r2), "=r"(r3) : "r"(a));
}

__device__ __forceinline__ uint32_t pack_bf16(float a, float b) {
    __nv_bfloat162 h = __floats2bfloat162_rn(a, b);
    return *reinterpret_cast<uint32_t*>(&h);
}

__device__ __forceinline__ void cp16(uint32_t smem, const void* g) {
    asm volatile("cp.async.cg.shared.global [%0], [%1], 16;\n"
                 :: "r"(smem), "l"(g));
}
__device__ __forceinline__ void cp_commit() {
    asm volatile("cp.async.commit_group;\n");
}
template <int N>
__device__ __forceinline__ void cp_wait() {
    asm volatile("cp.async.wait_group %0;\n" :: "n"(N));
}

#define LOG2E 1.4426950408889634f

// =============================================================================
// K0: w_final fp32 -> bf16 (one-time, tiny)
// =============================================================================
__global__ void wfconv_kernel(const float* __restrict__ wf) {
    int i = blockIdx.x * 256 + threadIdx.x;
    d_wfb[i] = __float2bfloat16(wf[i]);
}

// =============================================================================
// K1: projection GEMM + fused 2x2 maxpool, 3-stage cp.async pipeline.
// 256 threads, 8 warps (2m x 4n), warp tile 96x32. tf32 mma.  (round-8 proven)
// phi is emitted in mma-fragment order (see d_phi comment).
// =============================================================================
#define PJ_A_F   (192 * 40)
#define PJ_B_F   (32 * 132)
#define PJ_STAGE (PJ_A_F + PJ_B_F)           // floats
#define PJ_SMEM_B (3 * PJ_STAGE * 4)         // 142848 bytes (>= ytile 160*132*4)

__device__ __forceinline__ void proj_load(uint32_t a_s, uint32_t b_s,
                                          const float* wth, const float* wph,
                                          const float* wg, const float* xb,
                                          int kc, int p0, int tid) {
#pragma unroll
    for (int i = 0; i < 6; i++) {        // A: 192 rows x 32 floats
        int c = tid + i * 256;
        int r = c >> 3, q = c & 7;
        const float* src = (r < 32) ? wth + r * 256
                        : (r < 64) ? wph + (r - 32) * 256
                                   : wg + (r - 64) * 256;
        cp16(a_s + (r * 40 + q * 4) * 4, src + kc * 32 + q * 4);
    }
#pragma unroll
    for (int i = 0; i < 4; i++) {        // B: 32 rows x 128 floats
        int c = tid + i * 256;
        int kk = c >> 5, j4 = c & 31;
        cp16(b_s + (kk * 132 + j4 * 4) * 4,
             xb + (size_t)(kc * 32 + kk) * HW + p0 + j4 * 4);
    }
}

__global__ __launch_bounds__(256, 1)
void proj_kernel(const float* __restrict__ x,
                 const float* __restrict__ wth,
                 const float* __restrict__ wph,
                 const float* __restrict__ wg) {
    extern __shared__ float sm[];
    const uint32_t sm_u = (uint32_t)__cvta_generic_to_shared(sm);

    const int b   = blockIdx.y;
    const int p0  = blockIdx.x * 128;
    const int tid = threadIdx.x;
    const int w   = tid >> 5, lane = tid & 31;
    const int g   = lane >> 2, tig = lane & 3;
    const int wm  = w >> 2, wn = w & 3;
    const int m0w = wm * 96, n0w = wn * 32;

    float acc[6][4][4];
#pragma unroll
    for (int mt = 0; mt < 6; mt++)
#pragma unroll
        for (int nt = 0; nt < 4; nt++)
#pragma unroll
            for (int j = 0; j < 4; j++) acc[mt][nt][j] = 0.f;

    const float* xb = x + (size_t)b * C_IN * HW;

    proj_load(sm_u, sm_u + PJ_A_F * 4, wth, wph, wg, xb, 0, p0, tid);
    cp_commit();
    proj_load(sm_u + PJ_STAGE * 4, sm_u + (PJ_STAGE + PJ_A_F) * 4,
              wth, wph, wg, xb, 1, p0, tid);
    cp_commit();

    for (int kc = 0; kc < 8; kc++) {
        const int cur = kc % 3;
        if (kc + 2 < 8) {
            const int nst = (kc + 2) % 3;
            proj_load(sm_u + nst * PJ_STAGE * 4,
                      sm_u + (nst * PJ_STAGE + PJ_A_F) * 4,
                      wth, wph, wg, xb, kc + 2, p0, tid);
            cp_commit();
            cp_wait<2>();
        } else if (kc + 1 < 8) {
            cp_wait<1>();
        } else {
            cp_wait<0>();
        }
        __syncthreads();

        const float* Ac = sm + cur * PJ_STAGE;
        const float* Bc = sm + cur * PJ_STAGE + PJ_A_F;
#pragma unroll
        for (int ks = 0; ks < 4; ks++) {
            uint32_t a[6][4];
#pragma unroll
            for (int mt = 0; mt < 6; mt++) {
                int r = m0w + mt * 16;
                a[mt][0] = __float_as_uint(Ac[(r + g)     * 40 + ks * 8 + tig]);
                a[mt][1] = __float_as_uint(Ac[(r + g + 8) * 40 + ks * 8 + tig]);
                a[mt][2] = __float_as_uint(Ac[(r + g)     * 40 + ks * 8 + tig + 4]);
                a[mt][3] = __float_as_uint(Ac[(r + g + 8) * 40 + ks * 8 + tig + 4]);
            }
#pragma unroll
            for (int nt = 0; nt < 4; nt++) {
                uint32_t b0 = __float_as_uint(Bc[(ks * 8 + tig)     * 132 + n0w + nt * 8 + g]);
                uint32_t b1 = __float_as_uint(Bc[(ks * 8 + tig + 4) * 132 + n0w + nt * 8 + g]);
#pragma unroll
                for (int mt = 0; mt < 6; mt++) mma_tf32(acc[mt][nt], a[mt], b0, b1);
            }
        }
        __syncthreads();
    }

    // ---- epilogue: theta direct (transposed, rna); phi/g into smem ytile ----
    float* ytile = sm;   // 160 ch x 132 floats; staging buffers dead
    float* thb = d_theta + (size_t)b * HW * C8;
#pragma unroll
    for (int mt = 0; mt < 6; mt++)
#pragma unroll
        for (int nt = 0; nt < 4; nt++) {
            int pl = n0w + nt * 8 + tig * 2;
            int p  = p0 + pl;
            int c0 = m0w + mt * 16 + g;
            int c1 = c0 + 8;
            if (c0 < 32) {
                thb[(size_t)p * 32 + c0]       = tf32r(acc[mt][nt][0]);
                thb[(size_t)(p + 1) * 32 + c0] = tf32r(acc[mt][nt][1]);
                thb[(size_t)p * 32 + c1]       = tf32r(acc[mt][nt][2]);
                thb[(size_t)(p + 1) * 32 + c1] = tf32r(acc[mt][nt][3]);
            } else {
                ytile[(c0 - 32) * 132 + pl]     = acc[mt][nt][0];
                ytile[(c0 - 32) * 132 + pl + 1] = acc[mt][nt][1];
                ytile[(c1 - 32) * 132 + pl]     = acc[mt][nt][2];
                ytile[(c1 - 32) * 132 + pl + 1] = acc[mt][nt][3];
            }
        }
    __syncthreads();

    const int m0 = (p0 >> 2);   // 32 pooled keys per block
#pragma unroll
    for (int i = 0; i < 20; i++) {
        int idx = tid + i * 256;
        int ch = idx >> 5, wp = idx & 31;
        const float* r0 = &ytile[ch * 132 + wp * 2];
        float v = fmaxf(fmaxf(r0[0], r0[1]), fmaxf(r0[64], r0[65]));
        if (ch < 32) {
            // frag-ordered phi store
            int m    = m0 + wp;
            int tile = m >> 6, mk = m & 63;
            int nf   = mk >> 3, gg = mk & 7;
            int tg   = ch & 3, b2 = (ch >> 2) & 1, ks = ch >> 3;
            int lanei = gg * 4 + tg;
            d_phi[(size_t)b * 32768 + tile * 2048 + lanei * 64
                  + nf * 8 + ks * 2 + b2] = tf32r(v);
        } else {
            d_gT[((size_t)b * C2 + (ch - 32)) * MPOOL + m0 + wp] = __float2bfloat16(v);
        }
    }
}

// =============================================================================
// K2: fused flash attention + final 1x1 conv + residual.  (round-8 proven
// structure; QK B-frags now vectorized via frag-ordered phi: 16 LDS.128/tile)
// =============================================================================
#define KB       64
#define NTILE    (MPOOL / KB)        // 16
#define PH_LANE  272                 // bytes per lane block (256 + 16 pad)
#define G_STR    72
#define PH_BYTES (32 * PH_LANE)      // 8704
#define G_BYTES  (128 * G_STR * 2)   // 18432
#define K2_STAGE (PH_BYTES + G_BYTES)
#define K2_STG_T (3 * K2_STAGE)      // 81408 (also holds Osm 128*136*2=34816)
#define WF_STR   136
#define WF_BYTES (256 * WF_STR * 2)  // 69632
#define K2_SMEM  (K2_STG_T + WF_BYTES)  // 151040

__device__ __forceinline__ void attn_load_tile(uint32_t stage_base,
                                               const float* phb,
                                               const __nv_bfloat16* gTb,
                                               int mb, int tid) {
    const uint32_t ph_s = stage_base;
    const uint32_t g_s  = stage_base + PH_BYTES;
    // phi: frag-ordered tile = 2048 floats = 512 x 16B chunks; lane blocks padded
#pragma unroll
    for (int i = 0; i < 2; i++) {
        int c = tid + i * 256;
        int r = c >> 4, col = c & 15;
        cp16(ph_s + r * PH_LANE + col * 16,
             phb + (size_t)mb * 32 + c * 4);
    }
#pragma unroll
    for (int i = 0; i < 4; i++) {
        int c = tid + i * 256;
        int r = c >> 3, col = c & 7;
        cp16(g_s + r * (G_STR * 2) + col * 16,
             gTb + (size_t)r * MPOOL + mb + col * 8);
    }
}

__global__ __launch_bounds__(256, 1)
void attn_kernel(const float* __restrict__ x,
                 const float* __restrict__ sigp,
                 float* __restrict__ out) {
    extern __shared__ char smraw[];
    const uint32_t smem_u32 = (uint32_t)__cvta_generic_to_shared(smraw);
    const uint32_t wf_u = smem_u32 + K2_STG_T;

    const int b   = blockIdx.y, qt = blockIdx.x;
    const int tid = threadIdx.x;
    const int w   = tid >> 5, lane = tid & 31;
    const int g   = lane >> 2, tig = lane & 3;
    const int n0  = qt * 128 + w * 16;

    const float*         phb = d_phi + (size_t)b * 32 * MPOOL;
    const __nv_bfloat16* gTb = d_gT + (size_t)b * C2 * MPOOL;

    // ---- prefetch wf first (round-8 order), then first two tiles ----
#pragma unroll
    for (int i = 0; i < 16; i++) {
        int c = tid + i * 256;
        int r = c >> 4, q = c & 15;
        cp16(wf_u + (r * WF_STR + q * 8) * 2, d_wfb + (size_t)r * C2 + q * 8);
    }
    cp_commit();

    uint32_t at[4][4];
    {
        const float* th = d_theta + ((size_t)b * HW + n0) * 32;
#pragma unroll
        for (int ks = 0; ks < 4; ks++) {
            at[ks][0] = __float_as_uint(th[g * 32       + ks * 8 + tig]);
            at[ks][1] = __float_as_uint(th[(g + 8) * 32 + ks * 8 + tig]);
            at[ks][2] = __float_as_uint(th[g * 32       + ks * 8 + tig + 4]);
            at[ks][3] = __float_as_uint(th[(g + 8) * 32 + ks * 8 + tig + 4]);
        }
    }

    float O[16][4];
#pragma unroll
    for (int df = 0; df < 16; df++)
#pragma unroll
        for (int j = 0; j < 4; j++) O[df][j] = 0.f;
    float lsum0 = 0.f, lsum1 = 0.f;

    attn_load_tile(smem_u32, phb, gTb, 0, tid);
    cp_commit();
    attn_load_tile(smem_u32 + K2_STAGE, phb, gTb, KB, tid);
    cp_commit();

    for (int kb = 0; kb < NTILE; kb++) {
        const int cur = kb % 3;
        if (kb + 2 < NTILE) {
            attn_load_tile(smem_u32 + ((kb + 2) % 3) * K2_STAGE,
                           phb, gTb, (kb + 2) * KB, tid);
            cp_commit();
            cp_wait<2>();
        } else if (kb + 1 < NTILE) {
            cp_wait<1>();
        } else {
            cp_wait<0>();
        }
        __syncthreads();

        const uint32_t phc = smem_u32 + cur * K2_STAGE;
        const uint32_t gc  = phc + PH_BYTES;

        // ---- QK scores: frag-ordered phi, 2x LDS.128 + 4 mma per nf ----
        float S[8][4];
#pragma unroll
        for (int nf = 0; nf < 8; nf++)
            S[nf][0] = S[nf][1] = S[nf][2] = S[nf][3] = 0.f;
#pragma unroll
        for (int nf = 0; nf < 8; nf++) {
            uint32_t bb[8];
            uint32_t a0 = phc + lane * PH_LANE + nf * 32;
            lds_v4(bb[0], bb[1], bb[2], bb[3], a0);
            lds_v4(bb[4], bb[5], bb[6], bb[7], a0 + 16);
            mma_tf32(S[nf], at[0], bb[0], bb[1]);
            mma_tf32(S[nf], at[1], bb[2], bb[3]);
            mma_tf32(S[nf], at[2], bb[4], bb[5]);
            mma_tf32(S[nf], at[3], bb[6], bb[7]);
        }

#pragma unroll
        for (int nf = 0; nf < 8; nf++) {
            S[nf][0] = ex2(S[nf][0] * LOG2E);
            S[nf][1] = ex2(S[nf][1] * LOG2E);
            S[nf][2] = ex2(S[nf][2] * LOG2E);
            S[nf][3] = ex2(S[nf][3] * LOG2E);
            lsum0 += S[nf][0] + S[nf][1];
            lsum1 += S[nf][2] + S[nf][3];
        }

        uint32_t P[4][4];
#pragma unroll
        for (int kf = 0; kf < 4; kf++) {
            P[kf][0] = pack_bf16(S[2 * kf][0],     S[2 * kf][1]);
            P[kf][1] = pack_bf16(S[2 * kf][2],     S[2 * kf][3]);
            P[kf][2] = pack_bf16(S[2 * kf + 1][0], S[2 * kf + 1][1]);
            P[kf][3] = pack_bf16(S[2 * kf + 1][2], S[2 * kf + 1][3]);
        }

#pragma unroll
        for (int pair = 0; pair < 2; pair++) {
#pragma unroll
            for (int df = 0; df < 16; df++) {
                uint32_t r0, r1, r2, r3;
                uint32_t addr = gc +
                    ((df * 8 + (lane & 7)) * G_STR + pair * 32 + (lane >> 3) * 8) * 2;
                ldsm_x4(r0, r1, r2, r3, addr);
                mma_bf16(O[df], P[2 * pair],     r0, r1);
                mma_bf16(O[df], P[2 * pair + 1], r2, r3);
            }
        }
        __syncthreads();
    }

    // ---- normalize, O -> Osm (bf16, stride 136; staging area is dead) ----
    lsum0 += __shfl_xor_sync(0xffffffffu, lsum0, 1);
    lsum0 += __shfl_xor_sync(0xffffffffu, lsum0, 2);
    lsum1 += __shfl_xor_sync(0xffffffffu, lsum1, 1);
    lsum1 += __shfl_xor_sync(0xffffffffu, lsum1, 2);
    const float i0 = 1.f / lsum0, i1 = 1.f / lsum1;

    const uint32_t osm = smem_u32;
#pragma unroll
    for (int df = 0; df < 16; df++) {
        uint32_t v0 = pack_bf16(O[df][0] * i0, O[df][1] * i0);
        uint32_t v1 = pack_bf16(O[df][2] * i1, O[df][3] * i1);
        uint32_t a0 = osm + ((w * 16 + g) * WF_STR + df * 8 + tig * 2) * 2;
        asm volatile("st.shared.b32 [%0], %1;" :: "r"(a0), "r"(v0));
        asm volatile("st.shared.b32 [%0], %1;" :: "r"(a0 + 8 * WF_STR * 2), "r"(v1));
    }
    __syncthreads();

    // ---- final conv: out[256co x 128p] = sigma * wf @ Osm^T + x ----
    const float sig = *sigp;
    const int wm = w >> 1, wn = w & 1;
    const int cw = wm * 32, pw = wn * 64;

#pragma unroll
    for (int half = 0; half < 2; half++) {
        const int co0 = half * 128;
        float acc[2][8][4];
#pragma unroll
        for (int mt = 0; mt < 2; mt++)
#pragma unroll
            for (int nt = 0; nt < 8; nt++)
#pragma unroll
                for (int j = 0; j < 4; j++) acc[mt][nt][j] = 0.f;

#pragma unroll
        for (int k16 = 0; k16 < 8; k16++) {
            uint32_t a[2][4];
#pragma unroll
            for (int mt = 0; mt < 2; mt++) {
                uint32_t addr = wf_u +
                    ((co0 + cw + mt * 16 + (lane & 15)) * WF_STR + k16 * 16 + (lane >> 4) * 8) * 2;
                ldsm_x4(a[mt][0], a[mt][1], a[mt][2], a[mt][3], addr);
            }
            uint32_t bq[8][2];
#pragma unroll
            for (int nt = 0; nt < 8; nt++) {
                uint32_t addr = osm +
                    ((pw + nt * 8 + (lane & 7)) * WF_STR + k16 * 16 + ((lane >> 3) & 1) * 8) * 2;
                ldsm_x2(bq[nt][0], bq[nt][1], addr);
            }
#pragma unroll
            for (int nt = 0; nt < 8; nt++)
#pragma unroll
                for (int mt = 0; mt < 2; mt++)
                    mma_bf16(acc[mt][nt], a[mt], bq[nt][0], bq[nt][1]);
        }

#pragma unroll
        for (int mt = 0; mt < 2; mt++)
#pragma unroll
            for (int nt = 0; nt < 8; nt++) {
                int co = co0 + cw + mt * 16 + g;
                int p  = qt * 128 + pw + nt * 8 + tig * 2;
                {
                    size_t off = ((size_t)b * 256 + co) * HW + p;
                    float2 xv = *reinterpret_cast<const float2*>(&x[off]);
                    float2 ov = make_float2(sig * acc[mt][nt][0] + xv.x,
                                            sig * acc[mt][nt][1] + xv.y);
                    *reinterpret_cast<float2*>(&out[off]) = ov;
                }
                {
                    size_t off = ((size_t)b * 256 + co + 8) * HW + p;
                    float2 xv = *reinterpret_cast<const float2*>(&x[off]);
                    float2 ov = make_float2(sig * acc[mt][nt][2] + xv.x,
                                            sig * acc[mt][nt][3] + xv.y);
                    *reinterpret_cast<float2*>(&out[off]) = ov;
                }
            }
    }
}

// =============================================================================
extern "C" void kernel_launch(void* const* d_in, const int* in_sizes, int n_in,
                              void* d_out, int out_size) {
    (void)in_sizes; (void)n_in; (void)out_size;
    const float* x    = (const float*)d_in[0];
    const float* wth  = (const float*)d_in[1];
    const float* wph  = (const float*)d_in[2];
    const float* wg   = (const float*)d_in[3];
    const float* wf   = (const float*)d_in[4];
    const float* sig  = (const float*)d_in[5];
    float*       out  = (float*)d_out;

    cudaFuncSetAttribute(proj_kernel,
                         cudaFuncAttributeMaxDynamicSharedMemorySize, PJ_SMEM_B);
    cudaFuncSetAttribute(attn_kernel,
                         cudaFuncAttributeMaxDynamicSharedMemorySize, K2_SMEM);

    wfconv_kernel<<<(C_IN * C2) / 256, 256>>>(wf);
    proj_kernel<<<dim3(32, 16), 256, PJ_SMEM_B>>>(x, wth, wph, wg);
    attn_kernel<<<dim3(32, 16), 256, K2_SMEM>>>(x, sig, out);
}

// round 12
// speedup vs baseline: 1.2768x; 1.0349x over previous
#include <cuda_runtime.h>
#include <cuda_bf16.h>
#include <cstdint>

#define BATCH 16
#define C_IN  256
#define HW    4096
#define C8    32
#define C2    128
#define MPOOL 1024
#define CPROJ 192   // 32 theta + 32 phi + 128 g

// ---------------- scratch (device globals; no allocation allowed) ----------
// d_theta holds theta * log2(e) (tf32-rounded) so attn can use ex2 directly.
// d_phi is stored in mma-B-fragment order: per batch 16 key-tiles, per tile
// 32 lanes x 64 floats: value(lane=g*4+tig, i=nf*8+ks*2+b) = phi[kk=ks*8+tig+4b][key=nf*8+g]
__device__ float         d_theta[BATCH * HW * C8];
__device__ float         d_phi[BATCH * C8 * MPOOL];    // frag-ordered (see above)
__device__ __nv_bfloat16 d_gT[BATCH * C2 * MPOOL];     // [b][d][m]
__device__ __nv_bfloat16 d_wfb[C_IN * C2];             // bf16 copy of w_final

// ---------------- helpers ---------------------------------------------------
__device__ __forceinline__ float tf32r(float f) {
    uint32_t u;
    asm("cvt.rna.tf32.f32 %0, %1;" : "=r"(u) : "f"(f));
    return __uint_as_float(u);
}

__device__ __forceinline__ float ex2(float x) {
    float y;
    asm("ex2.approx.ftz.f32 %0, %1;" : "=f"(y) : "f"(x));
    return y;
}

__device__ __forceinline__ void mma_tf32(float* d, const uint32_t* a,
                                         uint32_t b0, uint32_t b1) {
    asm volatile(
        "mma.sync.aligned.m16n8k8.row.col.f32.tf32.tf32.f32 "
        "{%0,%1,%2,%3}, {%4,%5,%6,%7}, {%8,%9}, {%0,%1,%2,%3};"
        : "+f"(d[0]), "+f"(d[1]), "+f"(d[2]), "+f"(d[3])
        : "r"(a[0]), "r"(a[1]), "r"(a[2]), "r"(a[3]), "r"(b0), "r"(b1));
}

__device__ __forceinline__ void mma_bf16(float* d, const uint32_t* a,
                                         uint32_t b0, uint32_t b1) {
    asm volatile(
        "mma.sync.aligned.m16n8k16.row.col.f32.bf16.bf16.f32 "
        "{%0,%1,%2,%3}, {%4,%5,%6,%7}, {%8,%9}, {%0,%1,%2,%3};"
        : "+f"(d[0]), "+f"(d[1]), "+f"(d[2]), "+f"(d[3])
        : "r"(a[0]), "r"(a[1]), "r"(a[2]), "r"(a[3]), "r"(b0), "r"(b1));
}

__device__ __forceinline__ void ldsm_x4(uint32_t& r0, uint32_t& r1,
                                        uint32_t& r2, uint32_t& r3, uint32_t a) {
    asm volatile("ldmatrix.sync.aligned.m8n8.x4.shared.b16 {%0,%1,%2,%3}, [%4];"
                 : "=r"(r0), "=r"(r1), "=r"(r2), "=r"(r3) : "r"(a));
}
__device__ __forceinline__ void ldsm_x2(uint32_t& r0, uint32_t& r1, uint32_t a) {
    asm volatile("ldmatrix.sync.aligned.m8n8.x2.shared.b16 {%0,%1}, [%2];"
                 : "=r"(r0), "=r"(r1) : "r"(a));
}

__device__ __forceinline__ void lds_v4(uint32_t& r0, uint32_t& r1,
                                       uint32_t& r2, uint32_t& r3, uint32_t a) {
    asm volatile("ld.shared.v4.b32 {%0,%1,%2,%3}, [%4];"
                 : "=r"(r0), "=r"(r1), "=r"(r2), "=r"(r3) : "r"(a));
}

__device__ __forceinline__ uint32_t pack_bf16(float a, float b) {
    __nv_bfloat162 h = __floats2bfloat162_rn(a, b);
    return *reinterpret_cast<uint32_t*>(&h);
}

__device__ __forceinline__ void cp16(uint32_t smem, const void* g) {
    asm volatile("cp.async.cg.shared.global [%0], [%1], 16;\n"
                 :: "r"(smem), "l"(g));
}
__device__ __forceinline__ void cp_commit() {
    asm volatile("cp.async.commit_group;\n");
}
template <int N>
__device__ __forceinline__ void cp_wait() {
    asm volatile("cp.async.wait_group %0;\n" :: "n"(N));
}

#define LOG2E 1.4426950408889634f

// =============================================================================
// K1: projection GEMM + fused 2x2 maxpool, 3-stage cp.async pipeline.
// 256 threads, 8 warps (2m x 4n), warp tile 96x32. tf32 mma.
// Folds: wf fp32->bf16 conversion; theta scaled by log2(e) at store.
// =============================================================================
#define PJ_A_F   (192 * 40)
#define PJ_B_F   (32 * 132)
#define PJ_STAGE (PJ_A_F + PJ_B_F)           // floats
#define PJ_SMEM_B (3 * PJ_STAGE * 4)         // 142848 bytes (>= ytile 160*132*4)

__device__ __forceinline__ void proj_load(uint32_t a_s, uint32_t b_s,
                                          const float* wth, const float* wph,
                                          const float* wg, const float* xb,
                                          int kc, int p0, int tid) {
#pragma unroll
    for (int i = 0; i < 6; i++) {        // A: 192 rows x 32 floats
        int c = tid + i * 256;
        int r = c >> 3, q = c & 7;
        const float* src = (r < 32) ? wth + r * 256
                        : (r < 64) ? wph + (r - 32) * 256
                                   : wg + (r - 64) * 256;
        cp16(a_s + (r * 40 + q * 4) * 4, src + kc * 32 + q * 4);
    }
#pragma unroll
    for (int i = 0; i < 4; i++) {        // B: 32 rows x 128 floats
        int c = tid + i * 256;
        int kk = c >> 5, j4 = c & 31;
        cp16(b_s + (kk * 132 + j4 * 4) * 4,
             xb + (size_t)(kc * 32 + kk) * HW + p0 + j4 * 4);
    }
}

__global__ __launch_bounds__(256, 1)
void proj_kernel(const float* __restrict__ x,
                 const float* __restrict__ wth,
                 const float* __restrict__ wph,
                 const float* __restrict__ wg,
                 const float* __restrict__ wf) {
    extern __shared__ float sm[];
    const uint32_t sm_u = (uint32_t)__cvta_generic_to_shared(sm);

    const int b   = blockIdx.y;
    const int p0  = blockIdx.x * 128;
    const int tid = threadIdx.x;
    const int w   = tid >> 5, lane = tid & 31;
    const int g   = lane >> 2, tig = lane & 3;
    const int wm  = w >> 2, wn = w & 3;
    const int m0w = wm * 96, n0w = wn * 32;

    // ---- folded wfconv: this block's 64-element slice of w_final ----
    {
        int blk = b * 32 + blockIdx.x;            // 0..511
        if (tid < 16) {
            int e0 = blk * 64 + tid * 4;
            float4 v = *reinterpret_cast<const float4*>(&wf[e0]);
            uint2 pk = make_uint2(pack_bf16(v.x, v.y), pack_bf16(v.z, v.w));
            *reinterpret_cast<uint2*>(&d_wfb[e0]) = pk;
        }
    }

    float acc[6][4][4];
#pragma unroll
    for (int mt = 0; mt < 6; mt++)
#pragma unroll
        for (int nt = 0; nt < 4; nt++)
#pragma unroll
            for (int j = 0; j < 4; j++) acc[mt][nt][j] = 0.f;

    const float* xb = x + (size_t)b * C_IN * HW;

    proj_load(sm_u, sm_u + PJ_A_F * 4, wth, wph, wg, xb, 0, p0, tid);
    cp_commit();
    proj_load(sm_u + PJ_STAGE * 4, sm_u + (PJ_STAGE + PJ_A_F) * 4,
              wth, wph, wg, xb, 1, p0, tid);
    cp_commit();

    for (int kc = 0; kc < 8; kc++) {
        const int cur = kc % 3;
        if (kc + 2 < 8) {
            const int nst = (kc + 2) % 3;
            proj_load(sm_u + nst * PJ_STAGE * 4,
                      sm_u + (nst * PJ_STAGE + PJ_A_F) * 4,
                      wth, wph, wg, xb, kc + 2, p0, tid);
            cp_commit();
            cp_wait<2>();
        } else if (kc + 1 < 8) {
            cp_wait<1>();
        } else {
            cp_wait<0>();
        }
        __syncthreads();

        const float* Ac = sm + cur * PJ_STAGE;
        const float* Bc = sm + cur * PJ_STAGE + PJ_A_F;
#pragma unroll
        for (int ks = 0; ks < 4; ks++) {
            uint32_t a[6][4];
#pragma unroll
            for (int mt = 0; mt < 6; mt++) {
                int r = m0w + mt * 16;
                a[mt][0] = __float_as_uint(Ac[(r + g)     * 40 + ks * 8 + tig]);
                a[mt][1] = __float_as_uint(Ac[(r + g + 8) * 40 + ks * 8 + tig]);
                a[mt][2] = __float_as_uint(Ac[(r + g)     * 40 + ks * 8 + tig + 4]);
                a[mt][3] = __float_as_uint(Ac[(r + g + 8) * 40 + ks * 8 + tig + 4]);
            }
#pragma unroll
            for (int nt = 0; nt < 4; nt++) {
                uint32_t b0 = __float_as_uint(Bc[(ks * 8 + tig)     * 132 + n0w + nt * 8 + g]);
                uint32_t b1 = __float_as_uint(Bc[(ks * 8 + tig + 4) * 132 + n0w + nt * 8 + g]);
#pragma unroll
                for (int mt = 0; mt < 6; mt++) mma_tf32(acc[mt][nt], a[mt], b0, b1);
            }
        }
        __syncthreads();
    }

    // ---- epilogue: theta direct (transposed, *LOG2E, rna); phi/g -> ytile ----
    float* ytile = sm;   // 160 ch x 132 floats; staging buffers dead
    float* thb = d_theta + (size_t)b * HW * C8;
#pragma unroll
    for (int mt = 0; mt < 6; mt++)
#pragma unroll
        for (int nt = 0; nt < 4; nt++) {
            int pl = n0w + nt * 8 + tig * 2;
            int p  = p0 + pl;
            int c0 = m0w + mt * 16 + g;
            int c1 = c0 + 8;
            if (c0 < 32) {
                thb[(size_t)p * 32 + c0]       = tf32r(acc[mt][nt][0] * LOG2E);
                thb[(size_t)(p + 1) * 32 + c0] = tf32r(acc[mt][nt][1] * LOG2E);
                thb[(size_t)p * 32 + c1]       = tf32r(acc[mt][nt][2] * LOG2E);
                thb[(size_t)(p + 1) * 32 + c1] = tf32r(acc[mt][nt][3] * LOG2E);
            } else {
                ytile[(c0 - 32) * 132 + pl]     = acc[mt][nt][0];
                ytile[(c0 - 32) * 132 + pl + 1] = acc[mt][nt][1];
                ytile[(c1 - 32) * 132 + pl]     = acc[mt][nt][2];
                ytile[(c1 - 32) * 132 + pl + 1] = acc[mt][nt][3];
            }
        }
    __syncthreads();

    const int m0 = (p0 >> 2);   // 32 pooled keys per block
#pragma unroll
    for (int i = 0; i < 20; i++) {
        int idx = tid + i * 256;
        int ch = idx >> 5, wp = idx & 31;
        const float* r0 = &ytile[ch * 132 + wp * 2];
        float v = fmaxf(fmaxf(r0[0], r0[1]), fmaxf(r0[64], r0[65]));
        if (ch < 32) {
            // frag-ordered phi store
            int m    = m0 + wp;
            int tile = m >> 6, mk = m & 63;
            int nf   = mk >> 3, gg = mk & 7;
            int tg   = ch & 3, b2 = (ch >> 2) & 1, ks = ch >> 3;
            int lanei = gg * 4 + tg;
            d_phi[(size_t)b * 32768 + tile * 2048 + lanei * 64
                  + nf * 8 + ks * 2 + b2] = tf32r(v);
        } else {
            d_gT[((size_t)b * C2 + (ch - 32)) * MPOOL + m0 + wp] = __float2bfloat16(v);
        }
    }
}

// =============================================================================
// K2: fused flash attention + final 1x1 conv + residual.
// 4-stage cp.async pipeline; ONE __syncthreads per tile; prefetch of tile
// kb+3 issued AFTER the barrier (stage (kb+3)&3 == (kb-1)&3 is then provably
// no longer being read — that was the round-11 race).
// =============================================================================
#define KB       64
#define NTILE    (MPOOL / KB)        // 16
#define PH_LANE  272                 // bytes per lane block (256 + 16 pad)
#define G_STR    72
#define PH_BYTES (32 * PH_LANE)      // 8704
#define G_BYTES  (128 * G_STR * 2)   // 18432
#define K2_STAGE (PH_BYTES + G_BYTES)   // 27136
#define K2_NST   4
#define K2_STG_T (K2_NST * K2_STAGE)    // 108544 (Osm 34816 fits in stages 0-1)
#define WF_STR   136
#define WF_BYTES (256 * WF_STR * 2)     // 69632
#define K2_SMEM  (K2_STG_T + WF_BYTES)  // 178176

__device__ __forceinline__ void attn_load_tile(uint32_t stage_base,
                                               const float* phb,
                                               const __nv_bfloat16* gTb,
                                               int mb, int tid) {
    const uint32_t ph_s = stage_base;
    const uint32_t g_s  = stage_base + PH_BYTES;
#pragma unroll
    for (int i = 0; i < 2; i++) {
        int c = tid + i * 256;
        int r = c >> 4, col = c & 15;
        cp16(ph_s + r * PH_LANE + col * 16,
             phb + (size_t)mb * 32 + c * 4);
    }
#pragma unroll
    for (int i = 0; i < 4; i++) {
        int c = tid + i * 256;
        int r = c >> 3, col = c & 7;
        cp16(g_s + r * (G_STR * 2) + col * 16,
             gTb + (size_t)r * MPOOL + mb + col * 8);
    }
}

__global__ __launch_bounds__(256, 1)
void attn_kernel(const float* __restrict__ x,
                 const float* __restrict__ sigp,
                 float* __restrict__ out) {
    extern __shared__ char smraw[];
    const uint32_t smem_u32 = (uint32_t)__cvta_generic_to_shared(smraw);
    const uint32_t wf_u = smem_u32 + K2_STG_T;

    const int b   = blockIdx.y, qt = blockIdx.x;
    const int tid = threadIdx.x;
    const int w   = tid >> 5, lane = tid & 31;
    const int g   = lane >> 2, tig = lane & 3;
    const int n0  = qt * 128 + w * 16;

    const float*         phb = d_phi + (size_t)b * 32 * MPOOL;
    const __nv_bfloat16* gTb = d_gT + (size_t)b * C2 * MPOOL;

    // ---- prefetch wf first (oldest group), then first three tiles ----
#pragma unroll
    for (int i = 0; i < 16; i++) {
        int c = tid + i * 256;
        int r = c >> 4, q = c & 15;
        cp16(wf_u + (r * WF_STR + q * 8) * 2, d_wfb + (size_t)r * C2 + q * 8);
    }
    cp_commit();

    uint32_t at[4][4];
    {
        const float* th = d_theta + ((size_t)b * HW + n0) * 32;
#pragma unroll
        for (int ks = 0; ks < 4; ks++) {
            at[ks][0] = __float_as_uint(th[g * 32       + ks * 8 + tig]);
            at[ks][1] = __float_as_uint(th[(g + 8) * 32 + ks * 8 + tig]);
            at[ks][2] = __float_as_uint(th[g * 32       + ks * 8 + tig + 4]);
            at[ks][3] = __float_as_uint(th[(g + 8) * 32 + ks * 8 + tig + 4]);
        }
    }

    float O[16][4];
#pragma unroll
    for (int df = 0; df < 16; df++)
#pragma unroll
        for (int j = 0; j < 4; j++) O[df][j] = 0.f;
    float lsum0 = 0.f, lsum1 = 0.f;

    attn_load_tile(smem_u32, phb, gTb, 0, tid);
    cp_commit();
    attn_load_tile(smem_u32 + K2_STAGE, phb, gTb, KB, tid);
    cp_commit();
    attn_load_tile(smem_u32 + 2 * K2_STAGE, phb, gTb, 2 * KB, tid);
    cp_commit();

    for (int kb = 0; kb < NTILE; kb++) {
        const int cur = kb & 3;
        // outstanding groups at this point: tiles kb .. min(kb+2, NTILE-1)
        if (kb + 2 < NTILE)      cp_wait<2>();
        else if (kb + 1 < NTILE) cp_wait<1>();
        else                     cp_wait<0>();
        __syncthreads();   // single barrier per tile

        // prefetch AFTER the barrier: stage (kb+3)&3 == (kb-1)&3 was read in
        // iter kb-1, whose compute all warps finished before this barrier.
        if (kb + 3 < NTILE) {
            attn_load_tile(smem_u32 + ((kb + 3) & 3) * K2_STAGE,
                           phb, gTb, (kb + 3) * KB, tid);
            cp_commit();
        }

        const uint32_t phc = smem_u32 + cur * K2_STAGE;
        const uint32_t gc  = phc + PH_BYTES;

        // ---- QK scores: frag-ordered phi, 2x LDS.128 + 4 mma per nf ----
        float S[8][4];
#pragma unroll
        for (int nf = 0; nf < 8; nf++)
            S[nf][0] = S[nf][1] = S[nf][2] = S[nf][3] = 0.f;
#pragma unroll
        for (int nf = 0; nf < 8; nf++) {
            uint32_t bb[8];
            uint32_t a0 = phc + lane * PH_LANE + nf * 32;
            lds_v4(bb[0], bb[1], bb[2], bb[3], a0);
            lds_v4(bb[4], bb[5], bb[6], bb[7], a0 + 16);
            mma_tf32(S[nf], at[0], bb[0], bb[1]);
            mma_tf32(S[nf], at[1], bb[2], bb[3]);
            mma_tf32(S[nf], at[2], bb[4], bb[5]);
            mma_tf32(S[nf], at[3], bb[6], bb[7]);
        }

        // ---- exp: theta pre-scaled by log2e -> ex2 direct ----
#pragma unroll
        for (int nf = 0; nf < 8; nf++) {
            S[nf][0] = ex2(S[nf][0]);
            S[nf][1] = ex2(S[nf][1]);
            S[nf][2] = ex2(S[nf][2]);
            S[nf][3] = ex2(S[nf][3]);
            lsum0 += S[nf][0] + S[nf][1];
            lsum1 += S[nf][2] + S[nf][3];
        }

        uint32_t P[4][4];
#pragma unroll
        for (int kf = 0; kf < 4; kf++) {
            P[kf][0] = pack_bf16(S[2 * kf][0],     S[2 * kf][1]);
            P[kf][1] = pack_bf16(S[2 * kf][2],     S[2 * kf][3]);
            P[kf][2] = pack_bf16(S[2 * kf + 1][0], S[2 * kf + 1][1]);
            P[kf][3] = pack_bf16(S[2 * kf + 1][2], S[2 * kf + 1][3]);
        }

#pragma unroll
        for (int pair = 0; pair < 2; pair++) {
#pragma unroll
            for (int df = 0; df < 16; df++) {
                uint32_t r0, r1, r2, r3;
                uint32_t addr = gc +
                    ((df * 8 + (lane & 7)) * G_STR + pair * 32 + (lane >> 3) * 8) * 2;
                ldsm_x4(r0, r1, r2, r3, addr);
                mma_bf16(O[df], P[2 * pair],     r0, r1);
                mma_bf16(O[df], P[2 * pair + 1], r2, r3);
            }
        }
        // no end-of-iteration barrier needed: next iteration's prefetch is
        // issued only after the next top-of-loop __syncthreads.
    }

    // ---- normalize, O -> Osm (bf16, stride 136; stages 0-1 are >=2 iters cold)
    lsum0 += __shfl_xor_sync(0xffffffffu, lsum0, 1);
    lsum0 += __shfl_xor_sync(0xffffffffu, lsum0, 2);
    lsum1 += __shfl_xor_sync(0xffffffffu, lsum1, 1);
    lsum1 += __shfl_xor_sync(0xffffffffu, lsum1, 2);
    const float i0 = 1.f / lsum0, i1 = 1.f / lsum1;

    const uint32_t osm = smem_u32;
#pragma unroll
    for (int df = 0; df < 16; df++) {
        uint32_t v0 = pack_bf16(O[df][0] * i0, O[df][1] * i0);
        uint32_t v1 = pack_bf16(O[df][2] * i1, O[df][3] * i1);
        uint32_t a0 = osm + ((w * 16 + g) * WF_STR + df * 8 + tig * 2) * 2;
        asm volatile("st.shared.b32 [%0], %1;" :: "r"(a0), "r"(v0));
        asm volatile("st.shared.b32 [%0], %1;" :: "r"(a0 + 8 * WF_STR * 2), "r"(v1));
    }
    __syncthreads();

    // ---- final conv: out[256co x 128p] = sigma * wf @ Osm^T + x ----
    const float sig = *sigp;
    const int wm = w >> 1, wn = w & 1;
    const int cw = wm * 32, pw = wn * 64;

#pragma unroll
    for (int half = 0; half < 2; half++) {
        const int co0 = half * 128;
        float acc[2][8][4];
#pragma unroll
        for (int mt = 0; mt < 2; mt++)
#pragma unroll
            for (int nt = 0; nt < 8; nt++)
#pragma unroll
                for (int j = 0; j < 4; j++) acc[mt][nt][j] = 0.f;

#pragma unroll
        for (int k16 = 0; k16 < 8; k16++) {
            uint32_t a[2][4];
#pragma unroll
            for (int mt = 0; mt < 2; mt++) {
                uint32_t addr = wf_u +
                    ((co0 + cw + mt * 16 + (lane & 15)) * WF_STR + k16 * 16 + (lane >> 4) * 8) * 2;
                ldsm_x4(a[mt][0], a[mt][1], a[mt][2], a[mt][3], addr);
            }
            uint32_t bq[8][2];
#pragma unroll
            for (int nt = 0; nt < 8; nt++) {
                uint32_t addr = osm +
                    ((pw + nt * 8 + (lane & 7)) * WF_STR + k16 * 16 + ((lane >> 3) & 1) * 8) * 2;
                ldsm_x2(bq[nt][0], bq[nt][1], addr);
            }
#pragma unroll
            for (int nt = 0; nt < 8; nt++)
#pragma unroll
                for (int mt = 0; mt < 2; mt++)
                    mma_bf16(acc[mt][nt], a[mt], bq[nt][0], bq[nt][1]);
        }

#pragma unroll
        for (int mt = 0; mt < 2; mt++)
#pragma unroll
            for (int nt = 0; nt < 8; nt++) {
                int co = co0 + cw + mt * 16 + g;
                int p  = qt * 128 + pw + nt * 8 + tig * 2;
                {
                    size_t off = ((size_t)b * 256 + co) * HW + p;
                    float2 xv = *reinterpret_cast<const float2*>(&x[off]);
                    float2 ov = make_float2(sig * acc[mt][nt][0] + xv.x,
                                            sig * acc[mt][nt][1] + xv.y);
                    *reinterpret_cast<float2*>(&out[off]) = ov;
                }
                {
                    size_t off = ((size_t)b * 256 + co + 8) * HW + p;
                    float2 xv = *reinterpret_cast<const float2*>(&x[off]);
                    float2 ov = make_float2(sig * acc[mt][nt][2] + xv.x,
                                            sig * acc[mt][nt][3] + xv.y);
                    *reinterpret_cast<float2*>(&out[off]) = ov;
                }
            }
    }
}

// =============================================================================
extern "C" void kernel_launch(void* const* d_in, const int* in_sizes, int n_in,
                              void* d_out, int out_size) {
    (void)in_sizes; (void)n_in; (void)out_size;
    const float* x    = (const float*)d_in[0];
    const float* wth  = (const float*)d_in[1];
    const float* wph  = (const float*)d_in[2];
    const float* wg   = (const float*)d_in[3];
    const float* wf   = (const float*)d_in[4];
    const float* sig  = (const float*)d_in[5];
    float*       out  = (float*)d_out;

    cudaFuncSetAttribute(proj_kernel,
                         cudaFuncAttributeMaxDynamicSharedMemorySize, PJ_SMEM_B);
    cudaFuncSetAttribute(attn_kernel,
                         cudaFuncAttributeMaxDynamicSharedMemorySize, K2_SMEM);

    proj_kernel<<<dim3(32, 16), 256, PJ_SMEM_B>>>(x, wth, wph, wg, wf);
    attn_kernel<<<dim3(32, 16), 256, K2_SMEM>>>(x, sig, out);
}

// round 14
// speedup vs baseline: 1.3909x; 1.0894x over previous
#include <cuda_runtime.h>
#include <cuda_bf16.h>
#include <cstdint>

#define BATCH 16
#define C_IN  256
#define HW    4096
#define C8    32
#define C2    128
#define MPOOL 1024
#define CPROJ 192

// ---------------- scratch ----------------------------------------------------
// d_theta holds theta * log2(e) (tf32-rounded).
// d_phi frag-ordered: per batch 16 key-tiles, per tile 32 lanes x 64 floats.
__device__ float         d_theta[BATCH * HW * C8];
__device__ float         d_phi[BATCH * C8 * MPOOL];
__device__ __nv_bfloat16 d_gT[BATCH * C2 * MPOOL];     // [b][d][m]
__device__ __nv_bfloat16 d_wfb[C_IN * C2];             // bf16 w_final

// ---------------- helpers ----------------------------------------------------
__device__ __forceinline__ float tf32r(float f) {
    uint32_t u;
    asm("cvt.rna.tf32.f32 %0, %1;" : "=r"(u) : "f"(f));
    return __uint_as_float(u);
}
__device__ __forceinline__ float ex2(float x) {
    float y;
    asm("ex2.approx.ftz.f32 %0, %1;" : "=f"(y) : "f"(x));
    return y;
}
__device__ __forceinline__ void mma_tf32(float* d, const uint32_t* a,
                                         uint32_t b0, uint32_t b1) {
    asm volatile(
        "mma.sync.aligned.m16n8k8.row.col.f32.tf32.tf32.f32 "
        "{%0,%1,%2,%3}, {%4,%5,%6,%7}, {%8,%9}, {%0,%1,%2,%3};"
        : "+f"(d[0]), "+f"(d[1]), "+f"(d[2]), "+f"(d[3])
        : "r"(a[0]), "r"(a[1]), "r"(a[2]), "r"(a[3]), "r"(b0), "r"(b1));
}
__device__ __forceinline__ void mma_bf16(float* d, const uint32_t* a,
                                         uint32_t b0, uint32_t b1) {
    asm volatile(
        "mma.sync.aligned.m16n8k16.row.col.f32.bf16.bf16.f32 "
        "{%0,%1,%2,%3}, {%4,%5,%6,%7}, {%8,%9}, {%0,%1,%2,%3};"
        : "+f"(d[0]), "+f"(d[1]), "+f"(d[2]), "+f"(d[3])
        : "r"(a[0]), "r"(a[1]), "r"(a[2]), "r"(a[3]), "r"(b0), "r"(b1));
}
__device__ __forceinline__ void ldsm_x4(uint32_t& r0, uint32_t& r1,
                                        uint32_t& r2, uint32_t& r3, uint32_t a) {
    asm volatile("ldmatrix.sync.aligned.m8n8.x4.shared.b16 {%0,%1,%2,%3}, [%4];"
                 : "=r"(r0), "=r"(r1), "=r"(r2), "=r"(r3) : "r"(a));
}
__device__ __forceinline__ void ldsm_x2(uint32_t& r0, uint32_t& r1, uint32_t a) {
    asm volatile("ldmatrix.sync.aligned.m8n8.x2.shared.b16 {%0,%1}, [%2];"
                 : "=r"(r0), "=r"(r1) : "r"(a));
}
__device__ __forceinline__ void lds_v4(uint32_t& r0, uint32_t& r1,
                                       uint32_t& r2, uint32_t& r3, uint32_t a) {
    asm volatile("ld.shared.v4.b32 {%0,%1,%2,%3}, [%4];"
                 : "=r"(r0), "=r"(r1), "=r"(r2), "=r"(r3) : "r"(a));
}
__device__ __forceinline__ uint32_t pack_bf16(float a, float b) {
    __nv_bfloat162 h = __floats2bfloat162_rn(a, b);
    return *reinterpret_cast<uint32_t*>(&h);
}
__device__ __forceinline__ void cp16(uint32_t smem, const void* g) {
    asm volatile("cp.async.cg.shared.global [%0], [%1], 16;\n" :: "r"(smem), "l"(g));
}
__device__ __forceinline__ void cp_commit() {
    asm volatile("cp.async.commit_group;\n");
}
template <int N>
__device__ __forceinline__ void cp_wait() {
    asm volatile("cp.async.wait_group %0;\n" :: "n"(N));
}

#define LOG2E 1.4426950408889634f

// =============================================================================
// K1: projection GEMM + fused pool (round-12, unchanged; includes wf conv &
// theta*log2e prescale)
// =============================================================================
#define PJ_A_F   (192 * 40)
#define PJ_B_F   (32 * 132)
#define PJ_STAGE (PJ_A_F + PJ_B_F)
#define PJ_SMEM_B (3 * PJ_STAGE * 4)

__device__ __forceinline__ void proj_load(uint32_t a_s, uint32_t b_s,
                                          const float* wth, const float* wph,
                                          const float* wg, const float* xb,
                                          int kc, int p0, int tid) {
#pragma unroll
    for (int i = 0; i < 6; i++) {
        int c = tid + i * 256;
        int r = c >> 3, q = c & 7;
        const float* src = (r < 32) ? wth + r * 256
                        : (r < 64) ? wph + (r - 32) * 256
                                   : wg + (r - 64) * 256;
        cp16(a_s + (r * 40 + q * 4) * 4, src + kc * 32 + q * 4);
    }
#pragma unroll
    for (int i = 0; i < 4; i++) {
        int c = tid + i * 256;
        int kk = c >> 5, j4 = c & 31;
        cp16(b_s + (kk * 132 + j4 * 4) * 4,
             xb + (size_t)(kc * 32 + kk) * HW + p0 + j4 * 4);
    }
}

__global__ __launch_bounds__(256, 1)
void proj_kernel(const float* __restrict__ x,
                 const float* __restrict__ wth,
                 const float* __restrict__ wph,
                 const float* __restrict__ wg,
                 const float* __restrict__ wf) {
    extern __shared__ float sm[];
    const uint32_t sm_u = (uint32_t)__cvta_generic_to_shared(sm);

    const int b   = blockIdx.y;
    const int p0  = blockIdx.x * 128;
    const int tid = threadIdx.x;
    const int w   = tid >> 5, lane = tid & 31;
    const int g   = lane >> 2, tig = lane & 3;
    const int wm  = w >> 2, wn = w & 3;
    const int m0w = wm * 96, n0w = wn * 32;

    {
        int blk = b * 32 + blockIdx.x;
        if (tid < 16) {
            int e0 = blk * 64 + tid * 4;
            float4 v = *reinterpret_cast<const float4*>(&wf[e0]);
            uint2 pk = make_uint2(pack_bf16(v.x, v.y), pack_bf16(v.z, v.w));
            *reinterpret_cast<uint2*>(&d_wfb[e0]) = pk;
        }
    }

    float acc[6][4][4];
#pragma unroll
    for (int mt = 0; mt < 6; mt++)
#pragma unroll
        for (int nt = 0; nt < 4; nt++)
#pragma unroll
            for (int j = 0; j < 4; j++) acc[mt][nt][j] = 0.f;

    const float* xb = x + (size_t)b * C_IN * HW;

    proj_load(sm_u, sm_u + PJ_A_F * 4, wth, wph, wg, xb, 0, p0, tid);
    cp_commit();
    proj_load(sm_u + PJ_STAGE * 4, sm_u + (PJ_STAGE + PJ_A_F) * 4,
              wth, wph, wg, xb, 1, p0, tid);
    cp_commit();

    for (int kc = 0; kc < 8; kc++) {
        const int cur = kc % 3;
        if (kc + 2 < 8) {
            const int nst = (kc + 2) % 3;
            proj_load(sm_u + nst * PJ_STAGE * 4,
                      sm_u + (nst * PJ_STAGE + PJ_A_F) * 4,
                      wth, wph, wg, xb, kc + 2, p0, tid);
            cp_commit();
            cp_wait<2>();
        } else if (kc + 1 < 8) {
            cp_wait<1>();
        } else {
            cp_wait<0>();
        }
        __syncthreads();

        const float* Ac = sm + cur * PJ_STAGE;
        const float* Bc = sm + cur * PJ_STAGE + PJ_A_F;
#pragma unroll
        for (int ks = 0; ks < 4; ks++) {
            uint32_t a[6][4];
#pragma unroll
            for (int mt = 0; mt < 6; mt++) {
                int r = m0w + mt * 16;
                a[mt][0] = __float_as_uint(Ac[(r + g)     * 40 + ks * 8 + tig]);
                a[mt][1] = __float_as_uint(Ac[(r + g + 8) * 40 + ks * 8 + tig]);
                a[mt][2] = __float_as_uint(Ac[(r + g)     * 40 + ks * 8 + tig + 4]);
                a[mt][3] = __float_as_uint(Ac[(r + g + 8) * 40 + ks * 8 + tig + 4]);
            }
#pragma unroll
            for (int nt = 0; nt < 4; nt++) {
                uint32_t b0 = __float_as_uint(Bc[(ks * 8 + tig)     * 132 + n0w + nt * 8 + g]);
                uint32_t b1 = __float_as_uint(Bc[(ks * 8 + tig + 4) * 132 + n0w + nt * 8 + g]);
#pragma unroll
                for (int mt = 0; mt < 6; mt++) mma_tf32(acc[mt][nt], a[mt], b0, b1);
            }
        }
        __syncthreads();
    }

    float* ytile = sm;
    float* thb = d_theta + (size_t)b * HW * C8;
#pragma unroll
    for (int mt = 0; mt < 6; mt++)
#pragma unroll
        for (int nt = 0; nt < 4; nt++) {
            int pl = n0w + nt * 8 + tig * 2;
            int p  = p0 + pl;
            int c0 = m0w + mt * 16 + g;
            int c1 = c0 + 8;
            if (c0 < 32) {
                thb[(size_t)p * 32 + c0]       = tf32r(acc[mt][nt][0] * LOG2E);
                thb[(size_t)(p + 1) * 32 + c0] = tf32r(acc[mt][nt][1] * LOG2E);
                thb[(size_t)p * 32 + c1]       = tf32r(acc[mt][nt][2] * LOG2E);
                thb[(size_t)(p + 1) * 32 + c1] = tf32r(acc[mt][nt][3] * LOG2E);
            } else {
                ytile[(c0 - 32) * 132 + pl]     = acc[mt][nt][0];
                ytile[(c0 - 32) * 132 + pl + 1] = acc[mt][nt][1];
                ytile[(c1 - 32) * 132 + pl]     = acc[mt][nt][2];
                ytile[(c1 - 32) * 132 + pl + 1] = acc[mt][nt][3];
            }
        }
    __syncthreads();

    const int m0 = (p0 >> 2);
#pragma unroll
    for (int i = 0; i < 20; i++) {
        int idx = tid + i * 256;
        int ch = idx >> 5, wp = idx & 31;
        const float* r0 = &ytile[ch * 132 + wp * 2];
        float v = fmaxf(fmaxf(r0[0], r0[1]), fmaxf(r0[64], r0[65]));
        if (ch < 32) {
            int m    = m0 + wp;
            int tile = m >> 6, mk = m & 63;
            int nf   = mk >> 3, gg = mk & 7;
            int tg   = ch & 3, b2 = (ch >> 2) & 1, ks = ch >> 3;
            int lanei = gg * 4 + tg;
            d_phi[(size_t)b * 32768 + tile * 2048 + lanei * 64
                  + nf * 8 + ks * 2 + b2] = tf32r(v);
        } else {
            d_gT[((size_t)b * C2 + (ch - 32)) * MPOOL + m0 + wp] = __float2bfloat16(v);
        }
    }
}

// =============================================================================
// K2: flash attention + final conv + residual.  128 threads / 4 warps,
// q-tile 64, grid (64, 16) -> 2 CTAs per SM (regs & smem both fit).
// 4-stage cp.async ring, prefetch-after-barrier (round-12 proven discipline).
// wf staged at EPILOGUE into dead pipeline smem (keeps smem <= 106.5 KB).
// =============================================================================
#define KB       64
#define NTILE    16
#define PH_LANE  272
#define PH_BYTES (32 * PH_LANE)      // 8704
#define G_STR    72
#define G_BYTES  (128 * G_STR * 2)   // 18432
#define K2_STAGE (PH_BYTES + G_BYTES)   // 27136
#define K2_NST   4
#define K2_STG_T (K2_NST * K2_STAGE)    // 108544
#define LINV_OFF K2_STG_T               // 64 floats
#define K2_SMEM  (K2_STG_T + 512)       // 109056
// epilogue overlay (stages dead): wf @0 (69632 B), Osm @69632 (64*136*2=17408)
#define WF_STR   136
#define OSM_OFF  69632

__device__ __forceinline__ void attn_load_tile(uint32_t stage_base,
                                               const float* phb,
                                               const __nv_bfloat16* gTb,
                                               int mb, int tid) {
    const uint32_t ph_s = stage_base;
    const uint32_t g_s  = stage_base + PH_BYTES;
#pragma unroll
    for (int i = 0; i < 4; i++) {            // phi: 512 x 16B
        int c = tid + i * 128;
        int r = c >> 4, col = c & 15;
        cp16(ph_s + r * PH_LANE + col * 16, phb + (size_t)mb * 32 + c * 4);
    }
#pragma unroll
    for (int i = 0; i < 8; i++) {            // g: 1024 x 16B
        int c = tid + i * 128;
        int r = c >> 3, col = c & 7;
        cp16(g_s + r * (G_STR * 2) + col * 16,
             gTb + (size_t)r * MPOOL + mb + col * 8);
    }
}

__global__ __launch_bounds__(128, 2)
void attn_kernel(const float* __restrict__ x,
                 const float* __restrict__ sigp,
                 float* __restrict__ out) {
    extern __shared__ char smraw[];
    const uint32_t smem_u32 = (uint32_t)__cvta_generic_to_shared(smraw);

    const int b   = blockIdx.y, qt = blockIdx.x;
    const int tid = threadIdx.x;
    const int w   = tid >> 5, lane = tid & 31;     // w in 0..3
    const int g   = lane >> 2, tig = lane & 3;
    const int n0  = qt * 64 + w * 16;

    const float*         phb = d_phi + (size_t)b * 32 * MPOOL;
    const __nv_bfloat16* gTb = d_gT + (size_t)b * C2 * MPOOL;

    uint32_t at[4][4];
    {
        const float* th = d_theta + ((size_t)b * HW + n0) * 32;
#pragma unroll
        for (int ks = 0; ks < 4; ks++) {
            at[ks][0] = __float_as_uint(th[g * 32       + ks * 8 + tig]);
            at[ks][1] = __float_as_uint(th[(g + 8) * 32 + ks * 8 + tig]);
            at[ks][2] = __float_as_uint(th[g * 32       + ks * 8 + tig + 4]);
            at[ks][3] = __float_as_uint(th[(g + 8) * 32 + ks * 8 + tig + 4]);
        }
    }

    float O[16][4];
#pragma unroll
    for (int df = 0; df < 16; df++)
#pragma unroll
        for (int j = 0; j < 4; j++) O[df][j] = 0.f;
    float lsum0 = 0.f, lsum1 = 0.f;

    attn_load_tile(smem_u32, phb, gTb, 0, tid);
    cp_commit();
    attn_load_tile(smem_u32 + K2_STAGE, phb, gTb, KB, tid);
    cp_commit();
    attn_load_tile(smem_u32 + 2 * K2_STAGE, phb, gTb, 2 * KB, tid);
    cp_commit();

    for (int kb = 0; kb < NTILE; kb++) {
        const int cur = kb & 3;
        if (kb + 2 < NTILE)      cp_wait<2>();
        else if (kb + 1 < NTILE) cp_wait<1>();
        else                     cp_wait<0>();
        __syncthreads();

        if (kb + 3 < NTILE) {
            attn_load_tile(smem_u32 + ((kb + 3) & 3) * K2_STAGE,
                           phb, gTb, (kb + 3) * KB, tid);
            cp_commit();
        }

        const uint32_t phc = smem_u32 + cur * K2_STAGE;
        const uint32_t gc  = phc + PH_BYTES;

        float S[8][4];
#pragma unroll
        for (int nf = 0; nf < 8; nf++)
            S[nf][0] = S[nf][1] = S[nf][2] = S[nf][3] = 0.f;
#pragma unroll
        for (int nf = 0; nf < 8; nf++) {
            uint32_t bb[8];
            uint32_t a0 = phc + lane * PH_LANE + nf * 32;
            lds_v4(bb[0], bb[1], bb[2], bb[3], a0);
            lds_v4(bb[4], bb[5], bb[6], bb[7], a0 + 16);
            mma_tf32(S[nf], at[0], bb[0], bb[1]);
            mma_tf32(S[nf], at[1], bb[2], bb[3]);
            mma_tf32(S[nf], at[2], bb[4], bb[5]);
            mma_tf32(S[nf], at[3], bb[6], bb[7]);
        }

#pragma unroll
        for (int nf = 0; nf < 8; nf++) {
            S[nf][0] = ex2(S[nf][0]);
            S[nf][1] = ex2(S[nf][1]);
            S[nf][2] = ex2(S[nf][2]);
            S[nf][3] = ex2(S[nf][3]);
            lsum0 += S[nf][0] + S[nf][1];
            lsum1 += S[nf][2] + S[nf][3];
        }

        uint32_t P[4][4];
#pragma unroll
        for (int kf = 0; kf < 4; kf++) {
            P[kf][0] = pack_bf16(S[2 * kf][0],     S[2 * kf][1]);
            P[kf][1] = pack_bf16(S[2 * kf][2],     S[2 * kf][3]);
            P[kf][2] = pack_bf16(S[2 * kf + 1][0], S[2 * kf + 1][1]);
            P[kf][3] = pack_bf16(S[2 * kf + 1][2], S[2 * kf + 1][3]);
        }

#pragma unroll
        for (int pair = 0; pair < 2; pair++) {
#pragma unroll
            for (int df = 0; df < 16; df++) {
                uint32_t r0, r1, r2, r3;
                uint32_t addr = gc +
                    ((df * 8 + (lane & 7)) * G_STR + pair * 32 + (lane >> 3) * 8) * 2;
                ldsm_x4(r0, r1, r2, r3, addr);
                mma_bf16(O[df], P[2 * pair],     r0, r1);
                mma_bf16(O[df], P[2 * pair + 1], r2, r3);
            }
        }
    }

    // ---- epilogue: wf prefetch into dead stage smem ----
#pragma unroll
    for (int i = 0; i < 32; i++) {
        int c = tid + i * 128;
        int r = c >> 4, q = c & 15;
        cp16(smem_u32 + (r * WF_STR + q * 8) * 2, d_wfb + (size_t)r * C2 + q * 8);
    }
    cp_commit();

    // ---- normalize, O -> Osm (bf16) ----
    lsum0 += __shfl_xor_sync(0xffffffffu, lsum0, 1);
    lsum0 += __shfl_xor_sync(0xffffffffu, lsum0, 2);
    lsum1 += __shfl_xor_sync(0xffffffffu, lsum1, 1);
    lsum1 += __shfl_xor_sync(0xffffffffu, lsum1, 2);
    const float i0 = 1.f / lsum0, i1 = 1.f / lsum1;

    const uint32_t osm = smem_u32 + OSM_OFF;
#pragma unroll
    for (int df = 0; df < 16; df++) {
        uint32_t v0 = pack_bf16(O[df][0] * i0, O[df][1] * i0);
        uint32_t v1 = pack_bf16(O[df][2] * i1, O[df][3] * i1);
        uint32_t a0 = osm + ((w * 16 + g) * WF_STR + df * 8 + tig * 2) * 2;
        asm volatile("st.shared.b32 [%0], %1;" :: "r"(a0), "r"(v0));
        asm volatile("st.shared.b32 [%0], %1;" :: "r"(a0 + 8 * WF_STR * 2), "r"(v1));
    }
    cp_wait<0>();
    __syncthreads();

    // ---- final conv: out[256co x 64p] = sigma * wf @ Osm^T + x ----
    const float sig = *sigp;
    const uint32_t wf_u = smem_u32;
    const int wm = w >> 1, wn = w & 1;
    const int cw = wm * 32, pw = wn * 32;

#pragma unroll
    for (int half = 0; half < 4; half++) {
        const int co0 = half * 64;
        float acc[2][4][4];
#pragma unroll
        for (int mt = 0; mt < 2; mt++)
#pragma unroll
            for (int nt = 0; nt < 4; nt++)
#pragma unroll
                for (int j = 0; j < 4; j++) acc[mt][nt][j] = 0.f;

#pragma unroll
        for (int k16 = 0; k16 < 8; k16++) {
            uint32_t a[2][4];
#pragma unroll
            for (int mt = 0; mt < 2; mt++) {
                uint32_t addr = wf_u +
                    ((co0 + cw + mt * 16 + (lane & 15)) * WF_STR + k16 * 16 + (lane >> 4) * 8) * 2;
                ldsm_x4(a[mt][0], a[mt][1], a[mt][2], a[mt][3], addr);
            }
            uint32_t bq[4][2];
#pragma unroll
            for (int nt = 0; nt < 4; nt++) {
                uint32_t addr = osm +
                    ((pw + nt * 8 + (lane & 7)) * WF_STR + k16 * 16 + ((lane >> 3) & 1) * 8) * 2;
                ldsm_x2(bq[nt][0], bq[nt][1], addr);
            }
#pragma unroll
            for (int nt = 0; nt < 4; nt++)
#pragma unroll
                for (int mt = 0; mt < 2; mt++)
                    mma_bf16(acc[mt][nt], a[mt], bq[nt][0], bq[nt][1]);
        }

#pragma unroll
        for (int mt = 0; mt < 2; mt++)
#pragma unroll
            for (int nt = 0; nt < 4; nt++) {
                int co = co0 + cw + mt * 16 + g;
                int p  = qt * 64 + pw + nt * 8 + tig * 2;
                {
                    size_t off = ((size_t)b * 256 + co) * HW + p;
                    float2 xv = *reinterpret_cast<const float2*>(&x[off]);
                    float2 ov = make_float2(sig * acc[mt][nt][0] + xv.x,
                                            sig * acc[mt][nt][1] + xv.y);
                    *reinterpret_cast<float2*>(&out[off]) = ov;
                }
                {
                    size_t off = ((size_t)b * 256 + co + 8) * HW + p;
                    float2 xv = *reinterpret_cast<const float2*>(&x[off]);
                    float2 ov = make_float2(sig * acc[mt][nt][2] + xv.x,
                                            sig * acc[mt][nt][3] + xv.y);
                    *reinterpret_cast<float2*>(&out[off]) = ov;
                }
            }
    }
}

// =============================================================================
extern "C" void kernel_launch(void* const* d_in, const int* in_sizes, int n_in,
                              void* d_out, int out_size) {
    (void)in_sizes; (void)n_in; (void)out_size;
    const float* x    = (const float*)d_in[0];
    const float* wth  = (const float*)d_in[1];
    const float* wph  = (const float*)d_in[2];
    const float* wg   = (const float*)d_in[3];
    const float* wf   = (const float*)d_in[4];
    const float* sig  = (const float*)d_in[5];
    float*       out  = (float*)d_out;

    cudaFuncSetAttribute(proj_kernel,
                         cudaFuncAttributeMaxDynamicSharedMemorySize, PJ_SMEM_B);
    cudaFuncSetAttribute(attn_kernel,
                         cudaFuncAttributeMaxDynamicSharedMemorySize, K2_SMEM);

    proj_kernel<<<dim3(32, 16), 256, PJ_SMEM_B>>>(x, wth, wph, wg, wf);
    attn_kernel<<<dim3(64, 16), 128, K2_SMEM>>>(x, sig, out);
}

// round 15
// speedup vs baseline: 1.4106x; 1.0142x over previous
#include <cuda_runtime.h>
#include <cuda_bf16.h>
#include <cstdint>

#define BATCH 16
#define C_IN  256
#define HW    4096
#define C8    32
#define C2    128
#define MPOOL 1024
#define CPROJ 192

// ---------------- scratch ----------------------------------------------------
// d_theta holds theta * log2(e) (tf32-rounded).
// d_phi frag-ordered: per batch 16 key-tiles, per tile 32 lanes x 64 floats.
__device__ float         d_theta[BATCH * HW * C8];
__device__ float         d_phi[BATCH * C8 * MPOOL];
__device__ __nv_bfloat16 d_gT[BATCH * C2 * MPOOL];     // [b][d][m]
__device__ __nv_bfloat16 d_wfb[C_IN * C2];             // bf16 w_final

// ---------------- helpers ----------------------------------------------------
__device__ __forceinline__ float tf32r(float f) {
    uint32_t u;
    asm("cvt.rna.tf32.f32 %0, %1;" : "=r"(u) : "f"(f));
    return __uint_as_float(u);
}
__device__ __forceinline__ float ex2(float x) {
    float y;
    asm("ex2.approx.ftz.f32 %0, %1;" : "=f"(y) : "f"(x));
    return y;
}
__device__ __forceinline__ void mma_tf32(float* d, const uint32_t* a,
                                         uint32_t b0, uint32_t b1) {
    asm volatile(
        "mma.sync.aligned.m16n8k8.row.col.f32.tf32.tf32.f32 "
        "{%0,%1,%2,%3}, {%4,%5,%6,%7}, {%8,%9}, {%0,%1,%2,%3};"
        : "+f"(d[0]), "+f"(d[1]), "+f"(d[2]), "+f"(d[3])
        : "r"(a[0]), "r"(a[1]), "r"(a[2]), "r"(a[3]), "r"(b0), "r"(b1));
}
__device__ __forceinline__ void mma_bf16(float* d, const uint32_t* a,
                                         uint32_t b0, uint32_t b1) {
    asm volatile(
        "mma.sync.aligned.m16n8k16.row.col.f32.bf16.bf16.f32 "
        "{%0,%1,%2,%3}, {%4,%5,%6,%7}, {%8,%9}, {%0,%1,%2,%3};"
        : "+f"(d[0]), "+f"(d[1]), "+f"(d[2]), "+f"(d[3])
        : "r"(a[0]), "r"(a[1]), "r"(a[2]), "r"(a[3]), "r"(b0), "r"(b1));
}
__device__ __forceinline__ void ldsm_x4(uint32_t& r0, uint32_t& r1,
                                        uint32_t& r2, uint32_t& r3, uint32_t a) {
    asm volatile("ldmatrix.sync.aligned.m8n8.x4.shared.b16 {%0,%1,%2,%3}, [%4];"
                 : "=r"(r0), "=r"(r1), "=r"(r2), "=r"(r3) : "r"(a));
}
__device__ __forceinline__ void ldsm_x2(uint32_t& r0, uint32_t& r1, uint32_t a) {
    asm volatile("ldmatrix.sync.aligned.m8n8.x2.shared.b16 {%0,%1}, [%2];"
                 : "=r"(r0), "=r"(r1) : "r"(a));
}
__device__ __forceinline__ void lds_v4(uint32_t& r0, uint32_t& r1,
                                       uint32_t& r2, uint32_t& r3, uint32_t a) {
    asm volatile("ld.shared.v4.b32 {%0,%1,%2,%3}, [%4];"
                 : "=r"(r0), "=r"(r1), "=r"(r2), "=r"(r3) : "r"(a));
}
__device__ __forceinline__ uint32_t pack_bf16(float a, float b) {
    __nv_bfloat162 h = __floats2bfloat162_rn(a, b);
    return *reinterpret_cast<uint32_t*>(&h);
}
__device__ __forceinline__ void cp16(uint32_t smem, const void* g) {
    asm volatile("cp.async.cg.shared.global [%0], [%1], 16;\n" :: "r"(smem), "l"(g));
}
__device__ __forceinline__ void cp_commit() {
    asm volatile("cp.async.commit_group;\n");
}
template <int N>
__device__ __forceinline__ void cp_wait() {
    asm volatile("cp.async.wait_group %0;\n" :: "n"(N));
}

#define LOG2E 1.4426950408889634f

// =============================================================================
// K1: projection GEMM + fused pool, split over blockIdx.z (96 channels each)
// -> 2 CTAs per SM. 256 threads, 8 warps (2m x 4n), warp tile 48x32.
// z=0: theta(0-32) + phi(32-64) + g-ch(64-96); z=1: g-ch(96-192).
// =============================================================================
#define PJ_A_F   (96 * 40)                   // 3840 floats
#define PJ_B_F   (32 * 132)                  // 4224 floats
#define PJ_STAGE (PJ_A_F + PJ_B_F)           // 8064 floats = 32256 B
#define PJ_SMEM_B (3 * PJ_STAGE * 4)         // 96768 B (>= ytile 96*132*4=50688)

__device__ __forceinline__ void proj_load(uint32_t a_s, uint32_t b_s,
                                          const float* wth, const float* wph,
                                          const float* wg, const float* xb,
                                          int kc, int p0, int cb, int tid) {
#pragma unroll
    for (int i = 0; i < 3; i++) {        // A: 96 rows x 32 floats
        int c = tid + i * 256;
        int r = c >> 3, q = c & 7;
        int ch = cb + r;
        const float* src = (ch < 32) ? wth + ch * 256
                        : (ch < 64) ? wph + (ch - 32) * 256
                                    : wg + (ch - 64) * 256;
        cp16(a_s + (r * 40 + q * 4) * 4, src + kc * 32 + q * 4);
    }
#pragma unroll
    for (int i = 0; i < 4; i++) {        // B: 32 rows x 128 floats
        int c = tid + i * 256;
        int kk = c >> 5, j4 = c & 31;
        cp16(b_s + (kk * 132 + j4 * 4) * 4,
             xb + (size_t)(kc * 32 + kk) * HW + p0 + j4 * 4);
    }
}

__global__ __launch_bounds__(256, 2)
void proj_kernel(const float* __restrict__ x,
                 const float* __restrict__ wth,
                 const float* __restrict__ wph,
                 const float* __restrict__ wg,
                 const float* __restrict__ wf) {
    extern __shared__ float sm[];
    const uint32_t sm_u = (uint32_t)__cvta_generic_to_shared(sm);

    const int b   = blockIdx.y;
    const int p0  = blockIdx.x * 128;
    const int z   = blockIdx.z;
    const int cb  = z * 96;                  // channel base
    const int tid = threadIdx.x;
    const int w   = tid >> 5, lane = tid & 31;
    const int g   = lane >> 2, tig = lane & 3;
    const int wm  = w >> 2, wn = w & 3;
    const int m0w = wm * 48, n0w = wn * 32;

    // ---- folded wfconv (z=0 blocks cover all 32768 elements) ----
    if (z == 0 && tid < 16) {
        int blk = b * 32 + blockIdx.x;
        int e0 = blk * 64 + tid * 4;
        float4 v = *reinterpret_cast<const float4*>(&wf[e0]);
        uint2 pk = make_uint2(pack_bf16(v.x, v.y), pack_bf16(v.z, v.w));
        *reinterpret_cast<uint2*>(&d_wfb[e0]) = pk;
    }

    float acc[3][4][4];
#pragma unroll
    for (int mt = 0; mt < 3; mt++)
#pragma unroll
        for (int nt = 0; nt < 4; nt++)
#pragma unroll
            for (int j = 0; j < 4; j++) acc[mt][nt][j] = 0.f;

    const float* xb = x + (size_t)b * C_IN * HW;

    proj_load(sm_u, sm_u + PJ_A_F * 4, wth, wph, wg, xb, 0, p0, cb, tid);
    cp_commit();
    proj_load(sm_u + PJ_STAGE * 4, sm_u + (PJ_STAGE + PJ_A_F) * 4,
              wth, wph, wg, xb, 1, p0, cb, tid);
    cp_commit();

    for (int kc = 0; kc < 8; kc++) {
        const int cur = kc % 3;
        if (kc + 2 < 8) {
            const int nst = (kc + 2) % 3;
            proj_load(sm_u + nst * PJ_STAGE * 4,
                      sm_u + (nst * PJ_STAGE + PJ_A_F) * 4,
                      wth, wph, wg, xb, kc + 2, p0, cb, tid);
            cp_commit();
            cp_wait<2>();
        } else if (kc + 1 < 8) {
            cp_wait<1>();
        } else {
            cp_wait<0>();
        }
        __syncthreads();

        const float* Ac = sm + cur * PJ_STAGE;
        const float* Bc = sm + cur * PJ_STAGE + PJ_A_F;
#pragma unroll
        for (int ks = 0; ks < 4; ks++) {
            uint32_t a[3][4];
#pragma unroll
            for (int mt = 0; mt < 3; mt++) {
                int r = m0w + mt * 16;
                a[mt][0] = __float_as_uint(Ac[(r + g)     * 40 + ks * 8 + tig]);
                a[mt][1] = __float_as_uint(Ac[(r + g + 8) * 40 + ks * 8 + tig]);
                a[mt][2] = __float_as_uint(Ac[(r + g)     * 40 + ks * 8 + tig + 4]);
                a[mt][3] = __float_as_uint(Ac[(r + g + 8) * 40 + ks * 8 + tig + 4]);
            }
#pragma unroll
            for (int nt = 0; nt < 4; nt++) {
                uint32_t b0 = __float_as_uint(Bc[(ks * 8 + tig)     * 132 + n0w + nt * 8 + g]);
                uint32_t b1 = __float_as_uint(Bc[(ks * 8 + tig + 4) * 132 + n0w + nt * 8 + g]);
#pragma unroll
                for (int mt = 0; mt < 3; mt++) mma_tf32(acc[mt][nt], a[mt], b0, b1);
            }
        }
        __syncthreads();
    }

    // ---- epilogue ----
    float* ytile = sm;   // local pooled rows: z=0 -> 64 rows, z=1 -> 96 rows
    float* thb = d_theta + (size_t)b * HW * C8;
#pragma unroll
    for (int mt = 0; mt < 3; mt++)
#pragma unroll
        for (int nt = 0; nt < 4; nt++) {
            int pl = n0w + nt * 8 + tig * 2;
            int p  = p0 + pl;
            int c0 = m0w + mt * 16 + g;
            int c1 = c0 + 8;
            if (z == 0 && c0 < 32) {   // theta (c1 = c0+8 < 48 also theta iff c0<24: rows 0..47 -> both <48; theta is c<32)
                // c0 in [0,32): rows c0 and c1=c0+8; c1 may reach 39 >= 32 -> guard each
                thb[(size_t)p * 32 + c0]       = tf32r(acc[mt][nt][0] * LOG2E);
                thb[(size_t)(p + 1) * 32 + c0] = tf32r(acc[mt][nt][1] * LOG2E);
                if (c1 < 32) {
                    thb[(size_t)p * 32 + c1]       = tf32r(acc[mt][nt][2] * LOG2E);
                    thb[(size_t)(p + 1) * 32 + c1] = tf32r(acc[mt][nt][3] * LOG2E);
                } else {
                    ytile[(c1 - 32) * 132 + pl]     = acc[mt][nt][2];
                    ytile[(c1 - 32) * 132 + pl + 1] = acc[mt][nt][3];
                }
            } else {
                int l0 = c0 - (z ? 0 : 32);
                int l1 = c1 - (z ? 0 : 32);
                ytile[l0 * 132 + pl]     = acc[mt][nt][0];
                ytile[l0 * 132 + pl + 1] = acc[mt][nt][1];
                ytile[l1 * 132 + pl]     = acc[mt][nt][2];
                ytile[l1 * 132 + pl + 1] = acc[mt][nt][3];
            }
        }
    __syncthreads();

    const int m0 = (p0 >> 2);
    const int nch = z ? 96 : 64;       // pooled channels in this block
#pragma unroll
    for (int i = 0; i < 12; i++) {
        int idx = tid + i * 256;
        if (idx < nch * 32) {
            int ch = idx >> 5, wp = idx & 31;      // local pooled channel
            int pch = ch + (z ? 64 : 0);           // global pooled channel 0..159
            const float* r0 = &ytile[ch * 132 + wp * 2];
            float v = fmaxf(fmaxf(r0[0], r0[1]), fmaxf(r0[64], r0[65]));
            if (pch < 32) {
                int m    = m0 + wp;
                int tile = m >> 6, mk = m & 63;
                int nf   = mk >> 3, gg = mk & 7;
                int tg   = pch & 3, b2 = (pch >> 2) & 1, ks = pch >> 3;
                int lanei = gg * 4 + tg;
                d_phi[(size_t)b * 32768 + tile * 2048 + lanei * 64
                      + nf * 8 + ks * 2 + b2] = tf32r(v);
            } else {
                d_gT[((size_t)b * C2 + (pch - 32)) * MPOOL + m0 + wp] = __float2bfloat16(v);
            }
        }
    }
}

// =============================================================================
// K2: flash attention + final conv + residual (round-14, unchanged; 178.7 best)
// =============================================================================
#define KB       64
#define NTILE    16
#define PH_LANE  272
#define PH_BYTES (32 * PH_LANE)      // 8704
#define G_STR    72
#define G_BYTES  (128 * G_STR * 2)   // 18432
#define K2_STAGE (PH_BYTES + G_BYTES)   // 27136
#define K2_NST   4
#define K2_STG_T (K2_NST * K2_STAGE)    // 108544
#define K2_SMEM  (K2_STG_T + 512)       // 109056
#define WF_STR   136
#define OSM_OFF  69632

__device__ __forceinline__ void attn_load_tile(uint32_t stage_base,
                                               const float* phb,
                                               const __nv_bfloat16* gTb,
                                               int mb, int tid) {
    const uint32_t ph_s = stage_base;
    const uint32_t g_s  = stage_base + PH_BYTES;
#pragma unroll
    for (int i = 0; i < 4; i++) {
        int c = tid + i * 128;
        int r = c >> 4, col = c & 15;
        cp16(ph_s + r * PH_LANE + col * 16, phb + (size_t)mb * 32 + c * 4);
    }
#pragma unroll
    for (int i = 0; i < 8; i++) {
        int c = tid + i * 128;
        int r = c >> 3, col = c & 7;
        cp16(g_s + r * (G_STR * 2) + col * 16,
             gTb + (size_t)r * MPOOL + mb + col * 8);
    }
}

__global__ __launch_bounds__(128, 2)
void attn_kernel(const float* __restrict__ x,
                 const float* __restrict__ sigp,
                 float* __restrict__ out) {
    extern __shared__ char smraw[];
    const uint32_t smem_u32 = (uint32_t)__cvta_generic_to_shared(smraw);

    const int b   = blockIdx.y, qt = blockIdx.x;
    const int tid = threadIdx.x;
    const int w   = tid >> 5, lane = tid & 31;
    const int g   = lane >> 2, tig = lane & 3;
    const int n0  = qt * 64 + w * 16;

    const float*         phb = d_phi + (size_t)b * 32 * MPOOL;
    const __nv_bfloat16* gTb = d_gT + (size_t)b * C2 * MPOOL;

    uint32_t at[4][4];
    {
        const float* th = d_theta + ((size_t)b * HW + n0) * 32;
#pragma unroll
        for (int ks = 0; ks < 4; ks++) {
            at[ks][0] = __float_as_uint(th[g * 32       + ks * 8 + tig]);
            at[ks][1] = __float_as_uint(th[(g + 8) * 32 + ks * 8 + tig]);
            at[ks][2] = __float_as_uint(th[g * 32       + ks * 8 + tig + 4]);
            at[ks][3] = __float_as_uint(th[(g + 8) * 32 + ks * 8 + tig + 4]);
        }
    }

    float O[16][4];
#pragma unroll
    for (int df = 0; df < 16; df++)
#pragma unroll
        for (int j = 0; j < 4; j++) O[df][j] = 0.f;
    float lsum0 = 0.f, lsum1 = 0.f;

    attn_load_tile(smem_u32, phb, gTb, 0, tid);
    cp_commit();
    attn_load_tile(smem_u32 + K2_STAGE, phb, gTb, KB, tid);
    cp_commit();
    attn_load_tile(smem_u32 + 2 * K2_STAGE, phb, gTb, 2 * KB, tid);
    cp_commit();

    for (int kb = 0; kb < NTILE; kb++) {
        const int cur = kb & 3;
        if (kb + 2 < NTILE)      cp_wait<2>();
        else if (kb + 1 < NTILE) cp_wait<1>();
        else                     cp_wait<0>();
        __syncthreads();

        if (kb + 3 < NTILE) {
            attn_load_tile(smem_u32 + ((kb + 3) & 3) * K2_STAGE,
                           phb, gTb, (kb + 3) * KB, tid);
            cp_commit();
        }

        const uint32_t phc = smem_u32 + cur * K2_STAGE;
        const uint32_t gc  = phc + PH_BYTES;

        float S[8][4];
#pragma unroll
        for (int nf = 0; nf < 8; nf++)
            S[nf][0] = S[nf][1] = S[nf][2] = S[nf][3] = 0.f;
#pragma unroll
        for (int nf = 0; nf < 8; nf++) {
            uint32_t bb[8];
            uint32_t a0 = phc + lane * PH_LANE + nf * 32;
            lds_v4(bb[0], bb[1], bb[2], bb[3], a0);
            lds_v4(bb[4], bb[5], bb[6], bb[7], a0 + 16);
            mma_tf32(S[nf], at[0], bb[0], bb[1]);
            mma_tf32(S[nf], at[1], bb[2], bb[3]);
            mma_tf32(S[nf], at[2], bb[4], bb[5]);
            mma_tf32(S[nf], at[3], bb[6], bb[7]);
        }

#pragma unroll
        for (int nf = 0; nf < 8; nf++) {
            S[nf][0] = ex2(S[nf][0]);
            S[nf][1] = ex2(S[nf][1]);
            S[nf][2] = ex2(S[nf][2]);
            S[nf][3] = ex2(S[nf][3]);
            lsum0 += S[nf][0] + S[nf][1];
            lsum1 += S[nf][2] + S[nf][3];
        }

        uint32_t P[4][4];
#pragma unroll
        for (int kf = 0; kf < 4; kf++) {
            P[kf][0] = pack_bf16(S[2 * kf][0],     S[2 * kf][1]);
            P[kf][1] = pack_bf16(S[2 * kf][2],     S[2 * kf][3]);
            P[kf][2] = pack_bf16(S[2 * kf + 1][0], S[2 * kf + 1][1]);
            P[kf][3] = pack_bf16(S[2 * kf + 1][2], S[2 * kf + 1][3]);
        }

#pragma unroll
        for (int pair = 0; pair < 2; pair++) {
#pragma unroll
            for (int df = 0; df < 16; df++) {
                uint32_t r0, r1, r2, r3;
                uint32_t addr = gc +
                    ((df * 8 + (lane & 7)) * G_STR + pair * 32 + (lane >> 3) * 8) * 2;
                ldsm_x4(r0, r1, r2, r3, addr);
                mma_bf16(O[df], P[2 * pair],     r0, r1);
                mma_bf16(O[df], P[2 * pair + 1], r2, r3);
            }
        }
    }

    // ---- epilogue: wf prefetch into dead stage smem ----
#pragma unroll
    for (int i = 0; i < 32; i++) {
        int c = tid + i * 128;
        int r = c >> 4, q = c & 15;
        cp16(smem_u32 + (r * WF_STR + q * 8) * 2, d_wfb + (size_t)r * C2 + q * 8);
    }
    cp_commit();

    lsum0 += __shfl_xor_sync(0xffffffffu, lsum0, 1);
    lsum0 += __shfl_xor_sync(0xffffffffu, lsum0, 2);
    lsum1 += __shfl_xor_sync(0xffffffffu, lsum1, 1);
    lsum1 += __shfl_xor_sync(0xffffffffu, lsum1, 2);
    const float i0 = 1.f / lsum0, i1 = 1.f / lsum1;

    const uint32_t osm = smem_u32 + OSM_OFF;
#pragma unroll
    for (int df = 0; df < 16; df++) {
        uint32_t v0 = pack_bf16(O[df][0] * i0, O[df][1] * i0);
        uint32_t v1 = pack_bf16(O[df][2] * i1, O[df][3] * i1);
        uint32_t a0 = osm + ((w * 16 + g) * WF_STR + df * 8 + tig * 2) * 2;
        asm volatile("st.shared.b32 [%0], %1;" :: "r"(a0), "r"(v0));
        asm volatile("st.shared.b32 [%0], %1;" :: "r"(a0 + 8 * WF_STR * 2), "r"(v1));
    }
    cp_wait<0>();
    __syncthreads();

    const float sig = *sigp;
    const uint32_t wf_u = smem_u32;
    const int wm = w >> 1, wn = w & 1;
    const int cw = wm * 32, pw = wn * 32;

#pragma unroll
    for (int half = 0; half < 4; half++) {
        const int co0 = half * 64;
        float acc[2][4][4];
#pragma unroll
        for (int mt = 0; mt < 2; mt++)
#pragma unroll
            for (int nt = 0; nt < 4; nt++)
#pragma unroll
                for (int j = 0; j < 4; j++) acc[mt][nt][j] = 0.f;

#pragma unroll
        for (int k16 = 0; k16 < 8; k16++) {
            uint32_t a[2][4];
#pragma unroll
            for (int mt = 0; mt < 2; mt++) {
                uint32_t addr = wf_u +
                    ((co0 + cw + mt * 16 + (lane & 15)) * WF_STR + k16 * 16 + (lane >> 4) * 8) * 2;
                ldsm_x4(a[mt][0], a[mt][1], a[mt][2], a[mt][3], addr);
            }
            uint32_t bq[4][2];
#pragma unroll
            for (int nt = 0; nt < 4; nt++) {
                uint32_t addr = osm +
                    ((pw + nt * 8 + (lane & 7)) * WF_STR + k16 * 16 + ((lane >> 3) & 1) * 8) * 2;
                ldsm_x2(bq[nt][0], bq[nt][1], addr);
            }
#pragma unroll
            for (int nt = 0; nt < 4; nt++)
#pragma unroll
                for (int mt = 0; mt < 2; mt++)
                    mma_bf16(acc[mt][nt], a[mt], bq[nt][0], bq[nt][1]);
        }

#pragma unroll
        for (int mt = 0; mt < 2; mt++)
#pragma unroll
            for (int nt = 0; nt < 4; nt++) {
                int co = co0 + cw + mt * 16 + g;
                int p  = qt * 64 + pw + nt * 8 + tig * 2;
                {
                    size_t off = ((size_t)b * 256 + co) * HW + p;
                    float2 xv = *reinterpret_cast<const float2*>(&x[off]);
                    float2 ov = make_float2(sig * acc[mt][nt][0] + xv.x,
                                            sig * acc[mt][nt][1] + xv.y);
                    *reinterpret_cast<float2*>(&out[off]) = ov;
                }
                {
                    size_t off = ((size_t)b * 256 + co + 8) * HW + p;
                    float2 xv = *reinterpret_cast<const float2*>(&x[off]);
                    float2 ov = make_float2(sig * acc[mt][nt][2] + xv.x,
                                            sig * acc[mt][nt][3] + xv.y);
                    *reinterpret_cast<float2*>(&out[off]) = ov;
                }
            }
    }
}

// =============================================================================
extern "C" void kernel_launch(void* const* d_in, const int* in_sizes, int n_in,
                              void* d_out, int out_size) {
    (void)in_sizes; (void)n_in; (void)out_size;
    const float* x    = (const float*)d_in[0];
    const float* wth  = (const float*)d_in[1];
    const float* wph  = (const float*)d_in[2];
    const float* wg   = (const float*)d_in[3];
    const float* wf   = (const float*)d_in[4];
    const float* sig  = (const float*)d_in[5];
    float*       out  = (float*)d_out;

    cudaFuncSetAttribute(proj_kernel,
                         cudaFuncAttributeMaxDynamicSharedMemorySize, PJ_SMEM_B);
    cudaFuncSetAttribute(attn_kernel,
                         cudaFuncAttributeMaxDynamicSharedMemorySize, K2_SMEM);

    proj_kernel<<<dim3(32, 16, 2), 256, PJ_SMEM_B>>>(x, wth, wph, wg, wf);
    attn_kernel<<<dim3(64, 16), 128, K2_SMEM>>>(x, sig, out);
}

// round 16
// speedup vs baseline: 1.5313x; 1.0856x over previous
#include <cuda_runtime.h>
#include <cuda_bf16.h>
#include <cuda_fp16.h>
#include <cstdint>

#define BATCH 16
#define C_IN  256
#define HW    4096
#define C8    32
#define C2    128
#define MPOOL 1024
#define CPROJ 192

// ---------------- scratch ----------------------------------------------------
// d_theta_h: theta * log2(e), fp16, [b][n][32].
// d_phi_h: fp16, frag-ordered for mma.m16n8k16 B-operand: per batch 16 tiles,
//   per tile 32 lanes x 64 fp16; lane=gg*4+tig holds [nf][ks][hb][e]
//   (nf=key>>3 within tile, ks=ch>>4, hb=(ch&15)>>3, elem e=ch&1, tig=(ch&7)>>1).
__device__ __half         d_theta_h[BATCH * HW * C8];
__device__ __half         d_phi_h[BATCH * 32 * MPOOL];
__device__ __nv_bfloat16  d_gT[BATCH * C2 * MPOOL];     // [b][d][m]
__device__ __nv_bfloat16  d_wfb[C_IN * C2];             // bf16 w_final

// ---------------- helpers ----------------------------------------------------
__device__ __forceinline__ float tf32r(float f) {
    uint32_t u;
    asm("cvt.rna.tf32.f32 %0, %1;" : "=r"(u) : "f"(f));
    return __uint_as_float(u);
}
__device__ __forceinline__ float ex2(float x) {
    float y;
    asm("ex2.approx.ftz.f32 %0, %1;" : "=f"(y) : "f"(x));
    return y;
}
__device__ __forceinline__ void mma_tf32(float* d, const uint32_t* a,
                                         uint32_t b0, uint32_t b1) {
    asm volatile(
        "mma.sync.aligned.m16n8k8.row.col.f32.tf32.tf32.f32 "
        "{%0,%1,%2,%3}, {%4,%5,%6,%7}, {%8,%9}, {%0,%1,%2,%3};"
        : "+f"(d[0]), "+f"(d[1]), "+f"(d[2]), "+f"(d[3])
        : "r"(a[0]), "r"(a[1]), "r"(a[2]), "r"(a[3]), "r"(b0), "r"(b1));
}
__device__ __forceinline__ void mma_f16(float* d, const uint32_t* a,
                                        uint32_t b0, uint32_t b1) {
    asm volatile(
        "mma.sync.aligned.m16n8k16.row.col.f32.f16.f16.f32 "
        "{%0,%1,%2,%3}, {%4,%5,%6,%7}, {%8,%9}, {%0,%1,%2,%3};"
        : "+f"(d[0]), "+f"(d[1]), "+f"(d[2]), "+f"(d[3])
        : "r"(a[0]), "r"(a[1]), "r"(a[2]), "r"(a[3]), "r"(b0), "r"(b1));
}
__device__ __forceinline__ void mma_bf16(float* d, const uint32_t* a,
                                         uint32_t b0, uint32_t b1) {
    asm volatile(
        "mma.sync.aligned.m16n8k16.row.col.f32.bf16.bf16.f32 "
        "{%0,%1,%2,%3}, {%4,%5,%6,%7}, {%8,%9}, {%0,%1,%2,%3};"
        : "+f"(d[0]), "+f"(d[1]), "+f"(d[2]), "+f"(d[3])
        : "r"(a[0]), "r"(a[1]), "r"(a[2]), "r"(a[3]), "r"(b0), "r"(b1));
}
__device__ __forceinline__ void ldsm_x4(uint32_t& r0, uint32_t& r1,
                                        uint32_t& r2, uint32_t& r3, uint32_t a) {
    asm volatile("ldmatrix.sync.aligned.m8n8.x4.shared.b16 {%0,%1,%2,%3}, [%4];"
                 : "=r"(r0), "=r"(r1), "=r"(r2), "=r"(r3) : "r"(a));
}
__device__ __forceinline__ void ldsm_x2(uint32_t& r0, uint32_t& r1, uint32_t a) {
    asm volatile("ldmatrix.sync.aligned.m8n8.x2.shared.b16 {%0,%1}, [%2];"
                 : "=r"(r0), "=r"(r1) : "r"(a));
}
__device__ __forceinline__ void lds_v4(uint32_t& r0, uint32_t& r1,
                                       uint32_t& r2, uint32_t& r3, uint32_t a) {
    asm volatile("ld.shared.v4.b32 {%0,%1,%2,%3}, [%4];"
                 : "=r"(r0), "=r"(r1), "=r"(r2), "=r"(r3) : "r"(a));
}
__device__ __forceinline__ uint32_t pack_bf16(float a, float b) {
    __nv_bfloat162 h = __floats2bfloat162_rn(a, b);
    return *reinterpret_cast<uint32_t*>(&h);
}
__device__ __forceinline__ void cp16(uint32_t smem, const void* g) {
    asm volatile("cp.async.cg.shared.global [%0], [%1], 16;\n" :: "r"(smem), "l"(g));
}
__device__ __forceinline__ void cp_commit() {
    asm volatile("cp.async.commit_group;\n");
}
template <int N>
__device__ __forceinline__ void cp_wait() {
    asm volatile("cp.async.wait_group %0;\n" :: "n"(N));
}

#define LOG2E 1.4426950408889634f

// =============================================================================
// K1: projection GEMM + fused pool, split over blockIdx.z (96 channels each),
// 2 CTAs/SM (round-15). theta/phi now emitted as fp16.
// =============================================================================
#define PJ_A_F   (96 * 40)
#define PJ_B_F   (32 * 132)
#define PJ_STAGE (PJ_A_F + PJ_B_F)
#define PJ_SMEM_B (3 * PJ_STAGE * 4)

__device__ __forceinline__ void proj_load(uint32_t a_s, uint32_t b_s,
                                          const float* wth, const float* wph,
                                          const float* wg, const float* xb,
                                          int kc, int p0, int cb, int tid) {
#pragma unroll
    for (int i = 0; i < 3; i++) {
        int c = tid + i * 256;
        int r = c >> 3, q = c & 7;
        int ch = cb + r;
        const float* src = (ch < 32) ? wth + ch * 256
                        : (ch < 64) ? wph + (ch - 32) * 256
                                    : wg + (ch - 64) * 256;
        cp16(a_s + (r * 40 + q * 4) * 4, src + kc * 32 + q * 4);
    }
#pragma unroll
    for (int i = 0; i < 4; i++) {
        int c = tid + i * 256;
        int kk = c >> 5, j4 = c & 31;
        cp16(b_s + (kk * 132 + j4 * 4) * 4,
             xb + (size_t)(kc * 32 + kk) * HW + p0 + j4 * 4);
    }
}

__global__ __launch_bounds__(256, 2)
void proj_kernel(const float* __restrict__ x,
                 const float* __restrict__ wth,
                 const float* __restrict__ wph,
                 const float* __restrict__ wg,
                 const float* __restrict__ wf) {
    extern __shared__ float sm[];
    const uint32_t sm_u = (uint32_t)__cvta_generic_to_shared(sm);

    const int b   = blockIdx.y;
    const int p0  = blockIdx.x * 128;
    const int z   = blockIdx.z;
    const int cb  = z * 96;
    const int tid = threadIdx.x;
    const int w   = tid >> 5, lane = tid & 31;
    const int g   = lane >> 2, tig = lane & 3;
    const int wm  = w >> 2, wn = w & 3;
    const int m0w = wm * 48, n0w = wn * 32;

    if (z == 0 && tid < 16) {
        int blk = b * 32 + blockIdx.x;
        int e0 = blk * 64 + tid * 4;
        float4 v = *reinterpret_cast<const float4*>(&wf[e0]);
        uint2 pk = make_uint2(pack_bf16(v.x, v.y), pack_bf16(v.z, v.w));
        *reinterpret_cast<uint2*>(&d_wfb[e0]) = pk;
    }

    float acc[3][4][4];
#pragma unroll
    for (int mt = 0; mt < 3; mt++)
#pragma unroll
        for (int nt = 0; nt < 4; nt++)
#pragma unroll
            for (int j = 0; j < 4; j++) acc[mt][nt][j] = 0.f;

    const float* xb = x + (size_t)b * C_IN * HW;

    proj_load(sm_u, sm_u + PJ_A_F * 4, wth, wph, wg, xb, 0, p0, cb, tid);
    cp_commit();
    proj_load(sm_u + PJ_STAGE * 4, sm_u + (PJ_STAGE + PJ_A_F) * 4,
              wth, wph, wg, xb, 1, p0, cb, tid);
    cp_commit();

    for (int kc = 0; kc < 8; kc++) {
        const int cur = kc % 3;
        if (kc + 2 < 8) {
            const int nst = (kc + 2) % 3;
            proj_load(sm_u + nst * PJ_STAGE * 4,
                      sm_u + (nst * PJ_STAGE + PJ_A_F) * 4,
                      wth, wph, wg, xb, kc + 2, p0, cb, tid);
            cp_commit();
            cp_wait<2>();
        } else if (kc + 1 < 8) {
            cp_wait<1>();
        } else {
            cp_wait<0>();
        }
        __syncthreads();

        const float* Ac = sm + cur * PJ_STAGE;
        const float* Bc = sm + cur * PJ_STAGE + PJ_A_F;
#pragma unroll
        for (int ks = 0; ks < 4; ks++) {
            uint32_t a[3][4];
#pragma unroll
            for (int mt = 0; mt < 3; mt++) {
                int r = m0w + mt * 16;
                a[mt][0] = __float_as_uint(Ac[(r + g)     * 40 + ks * 8 + tig]);
                a[mt][1] = __float_as_uint(Ac[(r + g + 8) * 40 + ks * 8 + tig]);
                a[mt][2] = __float_as_uint(Ac[(r + g)     * 40 + ks * 8 + tig + 4]);
                a[mt][3] = __float_as_uint(Ac[(r + g + 8) * 40 + ks * 8 + tig + 4]);
            }
#pragma unroll
            for (int nt = 0; nt < 4; nt++) {
                uint32_t b0 = __float_as_uint(Bc[(ks * 8 + tig)     * 132 + n0w + nt * 8 + g]);
                uint32_t b1 = __float_as_uint(Bc[(ks * 8 + tig + 4) * 132 + n0w + nt * 8 + g]);
#pragma unroll
                for (int mt = 0; mt < 3; mt++) mma_tf32(acc[mt][nt], a[mt], b0, b1);
            }
        }
        __syncthreads();
    }

    // ---- epilogue ----
    float* ytile = sm;
    __half* thb = d_theta_h + (size_t)b * HW * C8;
#pragma unroll
    for (int mt = 0; mt < 3; mt++)
#pragma unroll
        for (int nt = 0; nt < 4; nt++) {
            int pl = n0w + nt * 8 + tig * 2;
            int p  = p0 + pl;
            int c0 = m0w + mt * 16 + g;
            int c1 = c0 + 8;
            if (z == 0 && c0 < 32) {
                thb[(size_t)p * 32 + c0]       = __float2half(acc[mt][nt][0] * LOG2E);
                thb[(size_t)(p + 1) * 32 + c0] = __float2half(acc[mt][nt][1] * LOG2E);
                if (c1 < 32) {
                    thb[(size_t)p * 32 + c1]       = __float2half(acc[mt][nt][2] * LOG2E);
                    thb[(size_t)(p + 1) * 32 + c1] = __float2half(acc[mt][nt][3] * LOG2E);
                } else {
                    ytile[(c1 - 32) * 132 + pl]     = acc[mt][nt][2];
                    ytile[(c1 - 32) * 132 + pl + 1] = acc[mt][nt][3];
                }
            } else {
                int l0 = c0 - (z ? 0 : 32);
                int l1 = c1 - (z ? 0 : 32);
                ytile[l0 * 132 + pl]     = acc[mt][nt][0];
                ytile[l0 * 132 + pl + 1] = acc[mt][nt][1];
                ytile[l1 * 132 + pl]     = acc[mt][nt][2];
                ytile[l1 * 132 + pl + 1] = acc[mt][nt][3];
            }
        }
    __syncthreads();

    const int m0 = (p0 >> 2);
    const int nch = z ? 96 : 64;
#pragma unroll
    for (int i = 0; i < 12; i++) {
        int idx = tid + i * 256;
        if (idx < nch * 32) {
            int ch = idx >> 5, wp = idx & 31;
            int pch = ch + (z ? 64 : 0);           // global pooled channel 0..159
            const float* r0 = &ytile[ch * 132 + wp * 2];
            float v = fmaxf(fmaxf(r0[0], r0[1]), fmaxf(r0[64], r0[65]));
            if (pch < 32) {
                // fp16 frag-ordered phi store (m16n8k16 B layout)
                int m    = m0 + wp;
                int tile = m >> 6, mk = m & 63;
                int nf   = mk >> 3, gg = mk & 7;
                int ks   = pch >> 4, kk = pch & 15;
                int hb   = kk >> 3;
                int tg   = (kk & 7) >> 1;
                int e    = kk & 1;
                int lanei = gg * 4 + tg;
                d_phi_h[(size_t)b * 32768 + tile * 2048 + lanei * 64
                        + nf * 8 + ks * 4 + hb * 2 + e] = __float2half(v);
            } else {
                d_gT[((size_t)b * C2 + (pch - 32)) * MPOOL + m0 + wp] = __float2bfloat16(v);
            }
        }
    }
}

// =============================================================================
// K2: flash attention (QK fp16 m16n8k16, PV bf16) + final conv + residual.
// 128 threads / 4 warps, q-tile 64, 2 CTAs/SM, 4-stage cp.async ring.
// =============================================================================
#define KB       64
#define NTILE    16
#define PH_LANE  144                 // 128 data + 16 pad bytes per lane
#define PH_BYTES (32 * PH_LANE)      // 4608
#define G_STR    72
#define G_BYTES  (128 * G_STR * 2)   // 18432
#define K2_STAGE (PH_BYTES + G_BYTES)   // 23040
#define K2_NST   4
#define K2_STG_T (K2_NST * K2_STAGE)    // 92160
#define K2_SMEM  (K2_STG_T + 512)       // 92672
#define WF_STR   136
#define OSM_OFF  69632                  // wf @0 (69632 B), Osm @69632 (17408 B)

__device__ __forceinline__ void attn_load_tile(uint32_t stage_base,
                                               const __half* phb,
                                               const __nv_bfloat16* gTb,
                                               int mb, int tid) {
    const uint32_t ph_s = stage_base;
    const uint32_t g_s  = stage_base + PH_BYTES;
#pragma unroll
    for (int i = 0; i < 2; i++) {            // phi: 256 x 16B chunks
        int c = tid + i * 128;
        int r = c >> 3, col = c & 7;
        cp16(ph_s + r * PH_LANE + col * 16, phb + (size_t)mb * 32 + c * 8);
    }
#pragma unroll
    for (int i = 0; i < 8; i++) {            // g: 1024 x 16B
        int c = tid + i * 128;
        int r = c >> 3, col = c & 7;
        cp16(g_s + r * (G_STR * 2) + col * 16,
             gTb + (size_t)r * MPOOL + mb + col * 8);
    }
}

__global__ __launch_bounds__(128, 2)
void attn_kernel(const float* __restrict__ x,
                 const float* __restrict__ sigp,
                 float* __restrict__ out) {
    extern __shared__ char smraw[];
    const uint32_t smem_u32 = (uint32_t)__cvta_generic_to_shared(smraw);

    const int b   = blockIdx.y, qt = blockIdx.x;
    const int tid = threadIdx.x;
    const int w   = tid >> 5, lane = tid & 31;
    const int g   = lane >> 2, tig = lane & 3;
    const int n0  = qt * 64 + w * 16;

    const __half*        phb = d_phi_h + (size_t)b * 32 * MPOOL;
    const __nv_bfloat16* gTb = d_gT + (size_t)b * C2 * MPOOL;

    // theta fp16 A-fragments for m16n8k16 (2 k-steps of 16)
    uint32_t at16[2][4];
    {
        const __half* th = d_theta_h + ((size_t)b * HW + n0) * 32;
#pragma unroll
        for (int ks = 0; ks < 2; ks++) {
            at16[ks][0] = *reinterpret_cast<const uint32_t*>(&th[g * 32       + ks * 16 + tig * 2]);
            at16[ks][1] = *reinterpret_cast<const uint32_t*>(&th[(g + 8) * 32 + ks * 16 + tig * 2]);
            at16[ks][2] = *reinterpret_cast<const uint32_t*>(&th[g * 32       + ks * 16 + 8 + tig * 2]);
            at16[ks][3] = *reinterpret_cast<const uint32_t*>(&th[(g + 8) * 32 + ks * 16 + 8 + tig * 2]);
        }
    }

    float O[16][4];
#pragma unroll
    for (int df = 0; df < 16; df++)
#pragma unroll
        for (int j = 0; j < 4; j++) O[df][j] = 0.f;
    float lsum0 = 0.f, lsum1 = 0.f;

    attn_load_tile(smem_u32, phb, gTb, 0, tid);
    cp_commit();
    attn_load_tile(smem_u32 + K2_STAGE, phb, gTb, KB, tid);
    cp_commit();
    attn_load_tile(smem_u32 + 2 * K2_STAGE, phb, gTb, 2 * KB, tid);
    cp_commit();

    for (int kb = 0; kb < NTILE; kb++) {
        const int cur = kb & 3;
        if (kb + 2 < NTILE)      cp_wait<2>();
        else if (kb + 1 < NTILE) cp_wait<1>();
        else                     cp_wait<0>();
        __syncthreads();

        if (kb + 3 < NTILE) {
            attn_load_tile(smem_u32 + ((kb + 3) & 3) * K2_STAGE,
                           phb, gTb, (kb + 3) * KB, tid);
            cp_commit();
        }

        const uint32_t phc = smem_u32 + cur * K2_STAGE;
        const uint32_t gc  = phc + PH_BYTES;

        // ---- QK: fp16 m16n8k16, 1 LDS.128 + 2 mma per nf ----
        float S[8][4];
#pragma unroll
        for (int nf = 0; nf < 8; nf++)
            S[nf][0] = S[nf][1] = S[nf][2] = S[nf][3] = 0.f;
#pragma unroll
        for (int nf = 0; nf < 8; nf++) {
            uint32_t u0, u1, u2, u3;
            lds_v4(u0, u1, u2, u3, phc + lane * PH_LANE + nf * 16);
            mma_f16(S[nf], at16[0], u0, u1);
            mma_f16(S[nf], at16[1], u2, u3);
        }

#pragma unroll
        for (int nf = 0; nf < 8; nf++) {
            S[nf][0] = ex2(S[nf][0]);
            S[nf][1] = ex2(S[nf][1]);
            S[nf][2] = ex2(S[nf][2]);
            S[nf][3] = ex2(S[nf][3]);
            lsum0 += S[nf][0] + S[nf][1];
            lsum1 += S[nf][2] + S[nf][3];
        }

        uint32_t P[4][4];
#pragma unroll
        for (int kf = 0; kf < 4; kf++) {
            P[kf][0] = pack_bf16(S[2 * kf][0],     S[2 * kf][1]);
            P[kf][1] = pack_bf16(S[2 * kf][2],     S[2 * kf][3]);
            P[kf][2] = pack_bf16(S[2 * kf + 1][0], S[2 * kf + 1][1]);
            P[kf][3] = pack_bf16(S[2 * kf + 1][2], S[2 * kf + 1][3]);
        }

#pragma unroll
        for (int pair = 0; pair < 2; pair++) {
#pragma unroll
            for (int df = 0; df < 16; df++) {
                uint32_t r0, r1, r2, r3;
                uint32_t addr = gc +
                    ((df * 8 + (lane & 7)) * G_STR + pair * 32 + (lane >> 3) * 8) * 2;
                ldsm_x4(r0, r1, r2, r3, addr);
                mma_bf16(O[df], P[2 * pair],     r0, r1);
                mma_bf16(O[df], P[2 * pair + 1], r2, r3);
            }
        }
    }

    // ---- epilogue: wf prefetch into dead stage smem ----
#pragma unroll
    for (int i = 0; i < 32; i++) {
        int c = tid + i * 128;
        int r = c >> 4, q = c & 15;
        cp16(smem_u32 + (r * WF_STR + q * 8) * 2, d_wfb + (size_t)r * C2 + q * 8);
    }
    cp_commit();

    lsum0 += __shfl_xor_sync(0xffffffffu, lsum0, 1);
    lsum0 += __shfl_xor_sync(0xffffffffu, lsum0, 2);
    lsum1 += __shfl_xor_sync(0xffffffffu, lsum1, 1);
    lsum1 += __shfl_xor_sync(0xffffffffu, lsum1, 2);
    const float i0 = 1.f / lsum0, i1 = 1.f / lsum1;

    const uint32_t osm = smem_u32 + OSM_OFF;
#pragma unroll
    for (int df = 0; df < 16; df++) {
        uint32_t v0 = pack_bf16(O[df][0] * i0, O[df][1] * i0);
        uint32_t v1 = pack_bf16(O[df][2] * i1, O[df][3] * i1);
        uint32_t a0 = osm + ((w * 16 + g) * WF_STR + df * 8 + tig * 2) * 2;
        asm volatile("st.shared.b32 [%0], %1;" :: "r"(a0), "r"(v0));
        asm volatile("st.shared.b32 [%0], %1;" :: "r"(a0 + 8 * WF_STR * 2), "r"(v1));
    }
    cp_wait<0>();
    __syncthreads();

    const float sig = *sigp;
    const uint32_t wf_u = smem_u32;
    const int wm = w >> 1, wn = w & 1;
    const int cw = wm * 32, pw = wn * 32;

#pragma unroll
    for (int half = 0; half < 4; half++) {
        const int co0 = half * 64;
        float acc[2][4][4];
#pragma unroll
        for (int mt = 0; mt < 2; mt++)
#pragma unroll
            for (int nt = 0; nt < 4; nt++)
#pragma unroll
                for (int j = 0; j < 4; j++) acc[mt][nt][j] = 0.f;

#pragma unroll
        for (int k16 = 0; k16 < 8; k16++) {
            uint32_t a[2][4];
#pragma unroll
            for (int mt = 0; mt < 2; mt++) {
                uint32_t addr = wf_u +
                    ((co0 + cw + mt * 16 + (lane & 15)) * WF_STR + k16 * 16 + (lane >> 4) * 8) * 2;
                ldsm_x4(a[mt][0], a[mt][1], a[mt][2], a[mt][3], addr);
            }
            uint32_t bq[4][2];
#pragma unroll
            for (int nt = 0; nt < 4; nt++) {
                uint32_t addr = osm +
                    ((pw + nt * 8 + (lane & 7)) * WF_STR + k16 * 16 + ((lane >> 3) & 1) * 8) * 2;
                ldsm_x2(bq[nt][0], bq[nt][1], addr);
            }
#pragma unroll
            for (int nt = 0; nt < 4; nt++)
#pragma unroll
                for (int mt = 0; mt < 2; mt++)
                    mma_bf16(acc[mt][nt], a[mt], bq[nt][0], bq[nt][1]);
        }

#pragma unroll
        for (int mt = 0; mt < 2; mt++)
#pragma unroll
            for (int nt = 0; nt < 4; nt++) {
                int co = co0 + cw + mt * 16 + g;
                int p  = qt * 64 + pw + nt * 8 + tig * 2;
                {
                    size_t off = ((size_t)b * 256 + co) * HW + p;
                    float2 xv = *reinterpret_cast<const float2*>(&x[off]);
                    float2 ov = make_float2(sig * acc[mt][nt][0] + xv.x,
                                            sig * acc[mt][nt][1] + xv.y);
                    *reinterpret_cast<float2*>(&out[off]) = ov;
                }
                {
                    size_t off = ((size_t)b * 256 + co + 8) * HW + p;
                    float2 xv = *reinterpret_cast<const float2*>(&x[off]);
                    float2 ov = make_float2(sig * acc[mt][nt][2] + xv.x,
                                            sig * acc[mt][nt][3] + xv.y);
                    *reinterpret_cast<float2*>(&out[off]) = ov;
                }
            }
    }
}

// =============================================================================
extern "C" void kernel_launch(void* const* d_in, const int* in_sizes, int n_in,
                              void* d_out, int out_size) {
    (void)in_sizes; (void)n_in; (void)out_size;
    const float* x    = (const float*)d_in[0];
    const float* wth  = (const float*)d_in[1];
    const float* wph  = (const float*)d_in[2];
    const float* wg   = (const float*)d_in[3];
    const float* wf   = (const float*)d_in[4];
    const float* sig  = (const float*)d_in[5];
    float*       out  = (float*)d_out;

    cudaFuncSetAttribute(proj_kernel,
                         cudaFuncAttributeMaxDynamicSharedMemorySize, PJ_SMEM_B);
    cudaFuncSetAttribute(attn_kernel,
                         cudaFuncAttributeMaxDynamicSharedMemorySize, K2_SMEM);

    proj_kernel<<<dim3(32, 16, 2), 256, PJ_SMEM_B>>>(x, wth, wph, wg, wf);
    attn_kernel<<<dim3(64, 16), 128, K2_SMEM>>>(x, sig, out);
}